// round 9
// baseline (speedup 1.0000x reference)
#include <cuda_runtime.h>
#include <cuda_bf16.h>
#include <math.h>
#include <stdint.h>

// Problem shapes (fixed per reference)
#define N_NODES 20000
#define N_EDGES 40000
#define H 64
#define F_ATOM 62
#define F_BOND 6
#define BGRAPH 512
#define HH 4096          // H*H
#define E_PAD 40064      // 626 * 64, padded edge count for 64-row MMA tiles

// ---------------- scratch (device globals; no allocs allowed) ----------------
__device__ float g_h[N_NODES * H];                    // node state (fp32)
__device__ float g_msg[N_NODES * H];                  // per-step message accumulator
__device__ float g_act[N_NODES * H];                  // atom activation
__device__ __nv_bfloat16 g_mlpb[E_PAD * H];           // edge MLP features (bf16)
__device__ __nv_bfloat16 g_EwB[HH * H];               // B operand: EwB[n=j*64+i][m] = Ew[m][i*64+j]
__device__ __nv_bfloat16 g_Abf[(size_t)E_PAD * HH];   // per-edge matrices, transposed: At[e][j*64+i], bf16
__device__ float g_gsum[BGRAPH * H];                  // graph segment sums

// ---------------- math helpers ----------------
__device__ __forceinline__ float selu_f(float x) {
    const float alpha = 1.6732632423543772f;
    const float scale = 1.0507009873554805f;
    return x > 0.f ? scale * x : scale * alpha * expm1f(x);
}

__device__ __forceinline__ void mma_bf16_16816(float c[4], const uint32_t a[4],
                                               const uint32_t b0, const uint32_t b1) {
    asm volatile(
        "mma.sync.aligned.m16n8k16.row.col.f32.bf16.bf16.f32 "
        "{%0,%1,%2,%3}, {%4,%5,%6,%7}, {%8,%9}, {%0,%1,%2,%3};"
        : "+f"(c[0]), "+f"(c[1]), "+f"(c[2]), "+f"(c[3])
        : "r"(a[0]), "r"(a[1]), "r"(a[2]), "r"(a[3]), "r"(b0), "r"(b1));
}

__device__ __forceinline__ void ldsm_x4(uint32_t r[4], uint32_t saddr) {
    asm volatile("ldmatrix.sync.aligned.m8n8.x4.shared.b16 {%0,%1,%2,%3}, [%4];"
                 : "=r"(r[0]), "=r"(r[1]), "=r"(r[2]), "=r"(r[3]) : "r"(saddr));
}

__global__ void k_zero(float* p, int n) {
    int i = blockIdx.x * blockDim.x + threadIdx.x;
    if (i < n) p[i] = 0.f;
}

// pad node features [N, F_ATOM] -> g_h [N, H]
__global__ void k_pad(const float* __restrict__ nf) {
    int idx = blockIdx.x * blockDim.x + threadIdx.x;
    if (idx >= N_NODES * H) return;
    int n = idx >> 6, c = idx & 63;
    g_h[idx] = (c < F_ATOM) ? nf[n * F_ATOM + c] : 0.f;
}

// mlp = relu(ef @ Wm + bm) -> bf16, padded edges write 0
__global__ void k_mlp(const float* __restrict__ ef, const float* __restrict__ Wm,
                      const float* __restrict__ bm) {
    __shared__ float s_ef[4][F_BOND];
    int tid = threadIdx.x;
    int sub = tid >> 6, i = tid & 63;
    int e = blockIdx.x * 4 + sub;
    if (i < F_BOND) s_ef[sub][i] = (e < N_EDGES) ? ef[e * F_BOND + i] : 0.f;
    __syncthreads();
    float v = bm[i];
#pragma unroll
    for (int f = 0; f < F_BOND; f++) v += s_ef[sub][f] * Wm[f * H + i];
    v = fmaxf(v, 0.f);
    if (e >= N_EDGES) v = 0.f;
    g_mlpb[e * H + i] = __float2bfloat16_rn(v);
}

// build B operand: g_EwB[n=j*64+i][m] = Ew[m][i*64+j]  (bf16)
__global__ void k_buildB(const float* __restrict__ Ew) {
    int o = blockIdx.x * blockDim.x + threadIdx.x;
    if (o >= HH * H) return;
    int n = o >> 6, m = o & 63;
    int j = n >> 6, i = n & 63;
    g_EwB[o] = __float2bfloat16_rn(Ew[(m << 12) + (i << 6) + j]);
}

// ============================================================================
// Fused: A = mlp @ EwB^T (bf16 HMMA) + step-1 edge messages.
// One CTA: 64 edges x full N=4096 (32 tiles of 128 cols). 256 threads, 8 warps
// (warp n-offset wn = wid*16). Per tile: MMA K=64, fold fp32 accums into
// register message partials (msg[e,i] += A[e,j*64+i]*h[rng[e],j]), stage C in
// smem (reusing the B buffer), write A rows fully coalesced. End: one
// atomicAdd per (e,i) slot into g_msg.
// ============================================================================
#define SROW 36   // padded operand row (u32 words); 144B -> 16B-aligned
#define CROW 68   // staged-C row (u32 words); 272B -> 16B-aligned
__global__ void __launch_bounds__(256) k_gemmA_fused(const int* __restrict__ dom,
                                                     const int* __restrict__ rng) {
    __shared__ __align__(16) uint32_t sA[64 * SROW];     // 9216 B
    __shared__ __align__(16) uint32_t sBC[128 * SROW];   // 18432 B; sB, reused as sC (64*CROW=17408B)
    __shared__ __align__(16) float sH[64][64];           // 16384 B: gathered h rows
    __shared__ int sD[64];                               // dom per edge
    int tid = threadIdx.x;
    int e0 = blockIdx.x * 64;

    // load A tile (64 rows x 64 bf16) = 512 uint4
    const uint4* gA = (const uint4*)(g_mlpb + (size_t)e0 * H);
#pragma unroll
    for (int it = 0; it < 2; it++) {
        int idx = it * 256 + tid;           // 0..511
        int row = idx >> 3, c4 = idx & 7;
        *(uint4*)&sA[row * SROW + c4 * 4] = gA[idx];
    }
    // gather h rows for the 64 edges (64 rows x 16 float4)
#pragma unroll
    for (int it = 0; it < 4; it++) {
        int idx = it * 256 + tid;           // 0..1023
        int e = idx >> 4, q = idx & 15;
        int ge = e0 + e;
        int r = (ge < N_EDGES) ? __ldg(&rng[ge]) : 0;
        ((float4*)sH[e])[q] = *(const float4*)(g_h + r * H + q * 4);
    }
    if (tid < 64) {
        int ge = e0 + tid;
        sD[tid] = (ge < N_EDGES) ? dom[ge] : 0;
    }

    int wid = tid >> 5, lane = tid & 31;
    int g = lane >> 2, tg = lane & 3;
    int wn = wid * 16;                      // warp covers 16 output cols
    int lrow = (lane & 7) + ((lane >> 3) & 1) * 8;
    int lcol = (lane >> 4) * 4;
    int j2 = (wn >= 64) ? 1 : 0;            // j parity owned by this warp

    uint32_t sA_u32 = (uint32_t)__cvta_generic_to_shared(sA);
    uint32_t sBC_u32 = (uint32_t)__cvta_generic_to_shared(sBC);

    float macc[4][2][4] = {};               // register message partials

    for (int nt = 0; nt < 32; nt++) {
        int n0 = nt * 128;
        __syncthreads();   // previous sC fully consumed
        // load B tile (128 n-rows x 64 bf16) = 1024 uint4
        const uint4* gB = (const uint4*)(g_EwB + (size_t)n0 * H);
#pragma unroll
        for (int it = 0; it < 4; it++) {
            int idx = it * 256 + tid;       // 0..1023
            int row = idx >> 3, c4 = idx & 7;
            *(uint4*)&sBC[row * SROW + c4 * 4] = gB[idx];
        }
        __syncthreads();

        float c[4][2][4] = {};
#pragma unroll
        for (int kk = 0; kk < 4; kk++) {
            uint32_t a[4][4];
#pragma unroll
            for (int mi = 0; mi < 4; mi++) {
                uint32_t addr = sA_u32 + ((mi * 16 + lrow) * SROW + kk * 8 + lcol) * 4;
                ldsm_x4(a[mi], addr);
            }
            uint32_t bq[4];                 // 16 n-rows for this warp
            {
                uint32_t addr = sBC_u32 + ((wn + lrow) * SROW + kk * 8 + lcol) * 4;
                ldsm_x4(bq, addr);
            }
#pragma unroll
            for (int mi = 0; mi < 4; mi++) {
                mma_bf16_16816(c[mi][0], a[mi], bq[0], bq[2]);
                mma_bf16_16816(c[mi][1], a[mi], bq[1], bq[3]);
            }
        }

        // fold into register message partials: j = 2*nt + j2 (fp32 A, fp32 h)
        {
            int j = 2 * nt + j2;
#pragma unroll
            for (int mi = 0; mi < 4; mi++) {
#pragma unroll
                for (int vh = 0; vh < 2; vh++) {
                    float hv = sH[mi * 16 + g + vh * 8][j];
#pragma unroll
                    for (int ni = 0; ni < 2; ni++) {
                        macc[mi][ni][vh * 2 + 0] = fmaf(c[mi][ni][vh * 2 + 0], hv, macc[mi][ni][vh * 2 + 0]);
                        macc[mi][ni][vh * 2 + 1] = fmaf(c[mi][ni][vh * 2 + 1], hv, macc[mi][ni][vh * 2 + 1]);
                    }
                }
            }
        }

        __syncthreads();   // all MMA reads of sBC done -> safe to stage C there
        uint32_t* sC = sBC;
#pragma unroll
        for (int mi = 0; mi < 4; mi++) {
            int r0 = mi * 16 + g;
#pragma unroll
            for (int ni = 0; ni < 2; ni++) {
                int cw = (wn >> 1) + ni * 4 + tg;
                __nv_bfloat162 lo = __float22bfloat162_rn(make_float2(c[mi][ni][0], c[mi][ni][1]));
                __nv_bfloat162 hi = __float22bfloat162_rn(make_float2(c[mi][ni][2], c[mi][ni][3]));
                sC[r0 * CROW + cw] = *(uint32_t*)&lo;
                sC[(r0 + 8) * CROW + cw] = *(uint32_t*)&hi;
            }
        }
        __syncthreads();
        // write-out: 64 rows x 256B contiguous = 1024 uint4
#pragma unroll
        for (int it = 0; it < 4; it++) {
            int idx = it * 256 + tid;       // 0..1023
            int row = idx >> 4, seg = idx & 15;
            uint4 v = *(uint4*)&sC[row * CROW + seg * 4];
            *(uint4*)(g_Abf + (size_t)(e0 + row) * HH + n0 + seg * 8) = v;
        }
    }

    // flush message partials (padded edges have mlp=0 -> macc=0 -> harmless)
#pragma unroll
    for (int mi = 0; mi < 4; mi++) {
#pragma unroll
        for (int ni = 0; ni < 2; ni++) {
#pragma unroll
            for (int v = 0; v < 4; v++) {
                int r = mi * 16 + g + ((v >> 1) & 1) * 8;
                int i = (wn + ni * 8 + tg * 2 + (v & 1)) & 63;
                atomicAdd(&g_msg[sD[r] * H + i], macc[mi][ni][v]);
            }
        }
    }
}

// edge pass (step 2 only): 8 edges per 256-thread block, streaming bf16x2 loads.
__global__ void __launch_bounds__(256) k_edge(const int* __restrict__ dom,
                                              const int* __restrict__ rng) {
    __shared__ float s_hj[8][64];
    int tid = threadIdx.x;
    int sub = tid >> 5, lane = tid & 31;
    int e = blockIdx.x * 8 + sub;
    int r = rng[e];
    float2 hv = *(const float2*)(g_h + r * H + 2 * lane);
    s_hj[sub][2 * lane] = hv.x;
    s_hj[sub][2 * lane + 1] = hv.y;
    __syncthreads();
    const unsigned int* Ae = (const unsigned int*)(g_Abf + (size_t)e * HH);
    float acc0 = 0.f, acc1 = 0.f;
#pragma unroll 8
    for (int j = 0; j < 64; j++) {
        unsigned int raw = __ldcs(&Ae[j * 32 + lane]);   // evict-first: A is stream-once
        __nv_bfloat162 a2 = *reinterpret_cast<__nv_bfloat162*>(&raw);
        float2 f = __bfloat1622float2(a2);
        float hjv = s_hj[sub][j];
        acc0 = fmaf(f.x, hjv, acc0);
        acc1 = fmaf(f.y, hjv, acc1);
    }
    int d = dom[e];
    atomicAdd(&g_msg[d * H + 2 * lane], acc0);
    atomicAdd(&g_msg[d * H + 2 * lane + 1], acc1);
}

// h = selu(msg @ Wu + bu + h); also resets msg to 0 for the next step/replay
__global__ void k_update(const float* __restrict__ Wu, const float* __restrict__ bu) {
    __shared__ float s_m[4][64];
    int tid = threadIdx.x;
    int sub = tid >> 6, i = tid & 63;
    int n = blockIdx.x * 4 + sub;
    int idx = n * H + i;
    s_m[sub][i] = g_msg[idx];
    g_msg[idx] = 0.f;
    __syncthreads();
    float acc = bu[i];
#pragma unroll 8
    for (int k = 0; k < 64; k++) acc = fmaf(s_m[sub][k], Wu[k * H + i], acc);
    g_h[idx] = selu_f(acc + g_h[idx]);
}

// act = selu((h @ Wae + bae) @ WR + bR)
__global__ void k_embed(const float* __restrict__ Wae, const float* __restrict__ bae,
                        const float* __restrict__ WR, const float* __restrict__ bR) {
    __shared__ float s_h[4][64];
    __shared__ float s_ae[4][64];
    int tid = threadIdx.x;
    int sub = tid >> 6, i = tid & 63;
    int n = blockIdx.x * 4 + sub;
    s_h[sub][i] = g_h[n * H + i];
    __syncthreads();
    float ae = bae[i];
#pragma unroll 8
    for (int k = 0; k < 64; k++) ae = fmaf(s_h[sub][k], Wae[k * H + i], ae);
    s_ae[sub][i] = ae;
    __syncthreads();
    float acc = bR[i];
#pragma unroll 8
    for (int k = 0; k < 64; k++) acc = fmaf(s_ae[sub][k], WR[k * H + i], acc);
    g_act[n * H + i] = selu_f(acc);
}

// segment-sum act over graph_id
__global__ void k_graphsum(const int* __restrict__ gid) {
    int idx = blockIdx.x * blockDim.x + threadIdx.x;
    if (idx >= N_NODES * H) return;
    int n = idx >> 6, i = idx & 63;
    atomicAdd(&g_gsum[gid[n] * H + i], g_act[idx]);
}

// out[b] = relu(tanh(gsum[b]) @ Wmlp + bmlp) @ Wout + bout
__global__ void k_readout(const float* __restrict__ Wmlp, const float* __restrict__ bmlp,
                          const float* __restrict__ Wout, const float* __restrict__ bout,
                          float* __restrict__ out) {
    __shared__ float s_ge[64];
    __shared__ float s_red[64];
    int b = blockIdx.x, i = threadIdx.x;
    s_ge[i] = tanhf(g_gsum[b * H + i]);
    __syncthreads();
    float acc = bmlp[i];
#pragma unroll 8
    for (int k = 0; k < 64; k++) acc = fmaf(s_ge[k], Wmlp[k * H + i], acc);
    float p = fmaxf(acc, 0.f) * Wout[i];
    s_red[i] = p;
    __syncthreads();
#pragma unroll
    for (int s = 32; s > 0; s >>= 1) {
        if (i < s) s_red[i] += s_red[i + s];
        __syncthreads();
    }
    if (i == 0) out[b] = s_red[0] + bout[0];
}

extern "C" void kernel_launch(void* const* d_in, const int* in_sizes, int n_in,
                              void* d_out, int out_size) {
    const float* node_features = (const float*)d_in[0];
    const float* edge_features = (const float*)d_in[1];
    const int*   edge_domain   = (const int*)d_in[2];
    const int*   edge_range    = (const int*)d_in[3];
    const int*   graph_id      = (const int*)d_in[4];
    const float* Wm   = (const float*)d_in[5];
    const float* bm   = (const float*)d_in[6];
    const float* Ew   = (const float*)d_in[7];
    const float* Wu0  = (const float*)d_in[8];
    const float* bu0  = (const float*)d_in[9];
    const float* Wu1  = (const float*)d_in[10];
    const float* bu1  = (const float*)d_in[11];
    const float* Wae  = (const float*)d_in[12];
    const float* bae  = (const float*)d_in[13];
    const float* WR   = (const float*)d_in[14];
    const float* bR   = (const float*)d_in[15];
    const float* Wmlp = (const float*)d_in[16];
    const float* bmlp = (const float*)d_in[17];
    const float* Wout = (const float*)d_in[18];
    const float* bout = (const float*)d_in[19];
    float* out = (float*)d_out;

    // prep
    k_pad<<<(N_NODES * H + 255) / 256, 256>>>(node_features);
    k_mlp<<<E_PAD / 4, 256>>>(edge_features, Wm, bm);
    k_buildB<<<(HH * H + 255) / 256, 256>>>(Ew);

    float* msg_ptr = nullptr;
    cudaGetSymbolAddress((void**)&msg_ptr, g_msg);
    float* gsum_ptr = nullptr;
    cudaGetSymbolAddress((void**)&gsum_ptr, g_gsum);

    k_zero<<<(N_NODES * H + 255) / 256, 256>>>(msg_ptr, N_NODES * H);

    // fused: A = mlp @ EwB^T (write bf16 A) + step-1 messages into g_msg
    k_gemmA_fused<<<E_PAD / 64, 256>>>(edge_domain, edge_range);
    k_update<<<N_NODES / 4, 256>>>(Wu0, bu0);   // h step 1; re-zeroes g_msg

    // step 2: explicit edge pass over stored A
    k_edge<<<N_EDGES / 8, 256>>>(edge_domain, edge_range);
    k_update<<<N_NODES / 4, 256>>>(Wu1, bu1);

    // readout
    k_embed<<<N_NODES / 4, 256>>>(Wae, bae, WR, bR);
    k_zero<<<(BGRAPH * H + 255) / 256, 256>>>(gsum_ptr, BGRAPH * H);
    k_graphsum<<<(N_NODES * H + 255) / 256, 256>>>(graph_id);
    k_readout<<<BGRAPH, 64>>>(Wmlp, bmlp, Wout, bout, out);
}

// round 10
// speedup vs baseline: 1.2831x; 1.2831x over previous
#include <cuda_runtime.h>
#include <cuda_bf16.h>
#include <math.h>
#include <stdint.h>

// Problem shapes (fixed per reference)
#define N_NODES 20000
#define N_EDGES 40000
#define H 64
#define F_ATOM 62
#define F_BOND 6
#define BGRAPH 512
#define HH 4096          // H*H
#define E_PAD 40064      // 313 * 128, padded edge count for 128-row MMA tiles

// ---------------- scratch (device globals; no allocs allowed) ----------------
__device__ float g_h[N_NODES * H];                    // node state (fp32)
__device__ float g_msg[N_NODES * H];                  // per-step message accumulator
__device__ float g_act[N_NODES * H];                  // atom activation
__device__ __nv_bfloat16 g_mlpb[E_PAD * H];           // edge MLP features (bf16)
__device__ __nv_bfloat16 g_EwB[HH * H];               // B operand: EwB[n=j*64+i][m] = Ew[m][i*64+j]
__device__ __nv_bfloat16 g_Abf[(size_t)E_PAD * HH];   // per-edge matrices, transposed: At[e][j*64+i], bf16
__device__ float g_gsum[BGRAPH * H];                  // graph segment sums

// ---------------- math helpers ----------------
__device__ __forceinline__ float selu_f(float x) {
    const float alpha = 1.6732632423543772f;
    const float scale = 1.0507009873554805f;
    return x > 0.f ? scale * x : scale * alpha * expm1f(x);
}

__device__ __forceinline__ void mma_bf16_16816(float c[4], const uint32_t a[4],
                                               const uint32_t b0, const uint32_t b1) {
    asm volatile(
        "mma.sync.aligned.m16n8k16.row.col.f32.bf16.bf16.f32 "
        "{%0,%1,%2,%3}, {%4,%5,%6,%7}, {%8,%9}, {%0,%1,%2,%3};"
        : "+f"(c[0]), "+f"(c[1]), "+f"(c[2]), "+f"(c[3])
        : "r"(a[0]), "r"(a[1]), "r"(a[2]), "r"(a[3]), "r"(b0), "r"(b1));
}

__device__ __forceinline__ void ldsm_x4(uint32_t r[4], uint32_t saddr) {
    asm volatile("ldmatrix.sync.aligned.m8n8.x4.shared.b16 {%0,%1,%2,%3}, [%4];"
                 : "=r"(r[0]), "=r"(r[1]), "=r"(r[2]), "=r"(r[3]) : "r"(saddr));
}

// ---------------- fused prep: pad h, edge MLP, build B, zero msg ----------------
#define PREP_PAD_BLKS 5000                  // N_NODES*H/256
#define PREP_MLP_BLKS (E_PAD / 4)           // 10016
#define PREP_B_BLKS 1024                    // H*HH/256
#define PREP_ZERO_BLKS 5000                 // N_NODES*H/256
#define PREP_GRID (PREP_PAD_BLKS + PREP_MLP_BLKS + PREP_B_BLKS + PREP_ZERO_BLKS)

__global__ void k_prep(const float* __restrict__ nf, const float* __restrict__ ef,
                       const float* __restrict__ Wm, const float* __restrict__ bm,
                       const float* __restrict__ Ew) {
    int b = blockIdx.x;
    int tid = threadIdx.x;
    if (b < PREP_PAD_BLKS) {
        int idx = b * 256 + tid;
        int n = idx >> 6, c = idx & 63;
        g_h[idx] = (c < F_ATOM) ? nf[n * F_ATOM + c] : 0.f;
    } else if (b < PREP_PAD_BLKS + PREP_MLP_BLKS) {
        __shared__ float s_ef[4][F_BOND];
        int eb = b - PREP_PAD_BLKS;
        int sub = tid >> 6, i = tid & 63;
        int e = eb * 4 + sub;
        if (i < F_BOND) s_ef[sub][i] = (e < N_EDGES) ? ef[e * F_BOND + i] : 0.f;
        __syncthreads();
        float v = bm[i];
#pragma unroll
        for (int f = 0; f < F_BOND; f++) v += s_ef[sub][f] * Wm[f * H + i];
        v = fmaxf(v, 0.f);
        if (e >= N_EDGES) v = 0.f;
        g_mlpb[e * H + i] = __float2bfloat16_rn(v);
    } else if (b < PREP_PAD_BLKS + PREP_MLP_BLKS + PREP_B_BLKS) {
        int o = (b - PREP_PAD_BLKS - PREP_MLP_BLKS) * 256 + tid;
        int n = o >> 6, m = o & 63;
        int j = n >> 6, i = n & 63;
        g_EwB[o] = __float2bfloat16_rn(Ew[(m << 12) + (i << 6) + j]);
    } else {
        int idx = (b - PREP_PAD_BLKS - PREP_MLP_BLKS - PREP_B_BLKS) * 256 + tid;
        g_msg[idx] = 0.f;
    }
}

// A = mlp[E,64] @ EwB^T via mma.sync bf16 (HMMA) with ldmatrix fragment loads
// and a smem-staged fully-coalesced epilogue. (R7-proven, unchanged.)
// CTA tile 128x128, K=64. 8 warps (2x4): warp tile 64x32.
#define SROW 36   // padded row (u32 words); 144B = 9*16B -> 16B-aligned rows
#define CROW 68   // staged-C row (u32 words); 272B = 17*16B -> 16B-aligned rows
__global__ void __launch_bounds__(256) k_gemmA_mma() {
    __shared__ __align__(16) uint32_t smem_all[2 * 128 * SROW];  // 36 KB
    uint32_t* sA = smem_all;
    uint32_t* sB = smem_all + 128 * SROW;
    int tid = threadIdx.x;
    int m0 = blockIdx.y * 128;   // edge tile
    int n0 = blockIdx.x * 128;   // output-col tile

    const uint4* gA = (const uint4*)(g_mlpb + (size_t)m0 * H);
    const uint4* gB = (const uint4*)(g_EwB + (size_t)n0 * H);
#pragma unroll
    for (int it = 0; it < 4; it++) {
        int idx = it * 256 + tid;      // 0..1023
        int row = idx >> 3, c = idx & 7;
        *(uint4*)&sA[row * SROW + c * 4] = gA[idx];
        *(uint4*)&sB[row * SROW + c * 4] = gB[idx];
    }
    __syncthreads();

    int wid = tid >> 5, lane = tid & 31;
    int g = lane >> 2, tg = lane & 3;
    int wm = (wid & 1) * 64;
    int wn = (wid >> 1) * 32;

    int lrow = (lane & 7) + ((lane >> 3) & 1) * 8;
    int lcol = (lane >> 4) * 4;

    uint32_t sA_u32 = (uint32_t)__cvta_generic_to_shared(sA);
    uint32_t sB_u32 = (uint32_t)__cvta_generic_to_shared(sB);

    float c[4][4][4] = {};
#pragma unroll
    for (int kk = 0; kk < 4; kk++) {
        uint32_t a[4][4];
#pragma unroll
        for (int mi = 0; mi < 4; mi++) {
            uint32_t addr = sA_u32 + ((wm + mi * 16 + lrow) * SROW + kk * 8 + lcol) * 4;
            ldsm_x4(a[mi], addr);
        }
        uint32_t bq[2][4];
#pragma unroll
        for (int nh = 0; nh < 2; nh++) {
            uint32_t addr = sB_u32 + ((wn + nh * 16 + lrow) * SROW + kk * 8 + lcol) * 4;
            ldsm_x4(bq[nh], addr);
        }
#pragma unroll
        for (int mi = 0; mi < 4; mi++) {
            mma_bf16_16816(c[mi][0], a[mi], bq[0][0], bq[0][2]);
            mma_bf16_16816(c[mi][1], a[mi], bq[0][1], bq[0][3]);
            mma_bf16_16816(c[mi][2], a[mi], bq[1][0], bq[1][2]);
            mma_bf16_16816(c[mi][3], a[mi], bq[1][1], bq[1][3]);
        }
    }

    __syncthreads();
    uint32_t* sC = smem_all;
#pragma unroll
    for (int mi = 0; mi < 4; mi++) {
        int r0 = wm + mi * 16 + g;
#pragma unroll
        for (int ni = 0; ni < 4; ni++) {
            int cw = (wn >> 1) + ni * 4 + tg;
            __nv_bfloat162 lo = __float22bfloat162_rn(make_float2(c[mi][ni][0], c[mi][ni][1]));
            __nv_bfloat162 hi = __float22bfloat162_rn(make_float2(c[mi][ni][2], c[mi][ni][3]));
            sC[r0 * CROW + cw] = *(uint32_t*)&lo;
            sC[(r0 + 8) * CROW + cw] = *(uint32_t*)&hi;
        }
    }
    __syncthreads();

    int half = lane >> 4;
    int seg = lane & 15;
#pragma unroll
    for (int r = 0; r < 8; r++) {
        int row = wid * 16 + 2 * r + half;
        uint4 v = *(uint4*)&sC[row * CROW + seg * 4];
        *(uint4*)(g_Abf + (size_t)(m0 + row) * HH + n0 + seg * 8) = v;
    }
}

// edge pass v2: 1 edge per warp, LDG.128 streaming loads, shfl reduction.
// lane = (jsub<<3)|iseg: per sweep s, j = s*4+jsub, lane loads 8 bf16 of row j
// (i = iseg*8..iseg*8+7). Warp address map = base + s*512 + lane*16: coalesced.
__global__ void __launch_bounds__(256) k_edge(const int* __restrict__ dom,
                                              const int* __restrict__ rng) {
    __shared__ float s_hj[8][64];
    int tid = threadIdx.x;
    int sub = tid >> 5, lane = tid & 31;
    int e = blockIdx.x * 8 + sub;
    int r = rng[e];
    float2 hv = *(const float2*)(g_h + r * H + 2 * lane);
    s_hj[sub][2 * lane] = hv.x;
    s_hj[sub][2 * lane + 1] = hv.y;
    __syncwarp();

    int iseg = lane & 7, jsub = lane >> 3;
    const uint4* Ae = (const uint4*)(g_Abf + (size_t)e * HH);
    float acc[8] = {};
#pragma unroll
    for (int s = 0; s < 16; s++) {
        int j = s * 4 + jsub;
        uint4 raw = __ldcs(&Ae[s * 32 + lane]);   // = row j, bytes iseg*16..: coalesced 512B/warp
        float hjv = s_hj[sub][j];
        const uint32_t w[4] = {raw.x, raw.y, raw.z, raw.w};
#pragma unroll
        for (int q = 0; q < 4; q++) {
            __nv_bfloat162 a2 = *reinterpret_cast<const __nv_bfloat162*>(&w[q]);
            float2 f = __bfloat1622float2(a2);
            acc[2 * q + 0] = fmaf(f.x, hjv, acc[2 * q + 0]);
            acc[2 * q + 1] = fmaf(f.y, hjv, acc[2 * q + 1]);
        }
    }
    // reduce across the 4 jsub groups (lane bits 3,4)
#pragma unroll
    for (int k = 0; k < 8; k++) {
        acc[k] += __shfl_xor_sync(0xFFFFFFFF, acc[k], 8);
        acc[k] += __shfl_xor_sync(0xFFFFFFFF, acc[k], 16);
    }
    // each lane flushes 2 of its octet's 8 slots: i = iseg*8 + jsub*2 + {0,1}
    int d = dom[e];
    int k0 = jsub * 2;
    atomicAdd(&g_msg[d * H + iseg * 8 + k0 + 0], acc[k0 + 0]);
    atomicAdd(&g_msg[d * H + iseg * 8 + k0 + 1], acc[k0 + 1]);
}

// h = selu(msg @ Wu + bu + h); also resets msg to 0 for the next step/replay
__global__ void k_update(const float* __restrict__ Wu, const float* __restrict__ bu) {
    __shared__ float s_m[4][64];
    int tid = threadIdx.x;
    int sub = tid >> 6, i = tid & 63;
    int n = blockIdx.x * 4 + sub;
    int idx = n * H + i;
    s_m[sub][i] = g_msg[idx];
    g_msg[idx] = 0.f;
    __syncthreads();
    float acc = bu[i];
#pragma unroll 8
    for (int k = 0; k < 64; k++) acc = fmaf(s_m[sub][k], Wu[k * H + i], acc);
    g_h[idx] = selu_f(acc + g_h[idx]);
}

// act = selu((h @ Wae + bae) @ WR + bR); blocks 0..127 also zero g_gsum
__global__ void k_embed(const float* __restrict__ Wae, const float* __restrict__ bae,
                        const float* __restrict__ WR, const float* __restrict__ bR) {
    __shared__ float s_h[4][64];
    __shared__ float s_ae[4][64];
    int tid = threadIdx.x;
    if (blockIdx.x < 128) g_gsum[blockIdx.x * 256 + tid] = 0.f;
    int sub = tid >> 6, i = tid & 63;
    int n = blockIdx.x * 4 + sub;
    s_h[sub][i] = g_h[n * H + i];
    __syncthreads();
    float ae = bae[i];
#pragma unroll 8
    for (int k = 0; k < 64; k++) ae = fmaf(s_h[sub][k], Wae[k * H + i], ae);
    s_ae[sub][i] = ae;
    __syncthreads();
    float acc = bR[i];
#pragma unroll 8
    for (int k = 0; k < 64; k++) acc = fmaf(s_ae[sub][k], WR[k * H + i], acc);
    g_act[n * H + i] = selu_f(acc);
}

// segment-sum act over graph_id
__global__ void k_graphsum(const int* __restrict__ gid) {
    int idx = blockIdx.x * blockDim.x + threadIdx.x;
    if (idx >= N_NODES * H) return;
    int n = idx >> 6, i = idx & 63;
    atomicAdd(&g_gsum[gid[n] * H + i], g_act[idx]);
}

// out[b] = relu(tanh(gsum[b]) @ Wmlp + bmlp) @ Wout + bout
__global__ void k_readout(const float* __restrict__ Wmlp, const float* __restrict__ bmlp,
                          const float* __restrict__ Wout, const float* __restrict__ bout,
                          float* __restrict__ out) {
    __shared__ float s_ge[64];
    __shared__ float s_red[64];
    int b = blockIdx.x, i = threadIdx.x;
    s_ge[i] = tanhf(g_gsum[b * H + i]);
    __syncthreads();
    float acc = bmlp[i];
#pragma unroll 8
    for (int k = 0; k < 64; k++) acc = fmaf(s_ge[k], Wmlp[k * H + i], acc);
    float p = fmaxf(acc, 0.f) * Wout[i];
    s_red[i] = p;
    __syncthreads();
#pragma unroll
    for (int s = 32; s > 0; s >>= 1) {
        if (i < s) s_red[i] += s_red[i + s];
        __syncthreads();
    }
    if (i == 0) out[b] = s_red[0] + bout[0];
}

extern "C" void kernel_launch(void* const* d_in, const int* in_sizes, int n_in,
                              void* d_out, int out_size) {
    const float* node_features = (const float*)d_in[0];
    const float* edge_features = (const float*)d_in[1];
    const int*   edge_domain   = (const int*)d_in[2];
    const int*   edge_range    = (const int*)d_in[3];
    const int*   graph_id      = (const int*)d_in[4];
    const float* Wm   = (const float*)d_in[5];
    const float* bm   = (const float*)d_in[6];
    const float* Ew   = (const float*)d_in[7];
    const float* Wu0  = (const float*)d_in[8];
    const float* bu0  = (const float*)d_in[9];
    const float* Wu1  = (const float*)d_in[10];
    const float* bu1  = (const float*)d_in[11];
    const float* Wae  = (const float*)d_in[12];
    const float* bae  = (const float*)d_in[13];
    const float* WR   = (const float*)d_in[14];
    const float* bR   = (const float*)d_in[15];
    const float* Wmlp = (const float*)d_in[16];
    const float* bmlp = (const float*)d_in[17];
    const float* Wout = (const float*)d_in[18];
    const float* bout = (const float*)d_in[19];
    float* out = (float*)d_out;

    // fused prep: pad h, edge MLP, build B operand, zero g_msg
    k_prep<<<PREP_GRID, 256>>>(node_features, edge_features, Wm, bm, Ew);

    // A = mlp @ EwB^T on tensor cores (bf16 HMMA, fp32 accumulate, bf16 out)
    dim3 gA(HH / 128, E_PAD / 128);
    k_gemmA_mma<<<gA, 256>>>();

    // message passing steps
    const float* Wus[2] = {Wu0, Wu1};
    const float* bus[2] = {bu0, bu1};
    for (int t = 0; t < 2; t++) {
        k_edge<<<N_EDGES / 8, 256>>>(edge_domain, edge_range);
        k_update<<<N_NODES / 4, 256>>>(Wus[t], bus[t]);  // also re-zeroes g_msg
    }

    // readout
    k_embed<<<N_NODES / 4, 256>>>(Wae, bae, WR, bR);     // also zeroes g_gsum
    k_graphsum<<<(N_NODES * H + 255) / 256, 256>>>(graph_id);
    k_readout<<<BGRAPH, 64>>>(Wmlp, bmlp, Wout, bout, out);
}

// round 11
// speedup vs baseline: 1.3193x; 1.0282x over previous
#include <cuda_runtime.h>
#include <cuda_bf16.h>
#include <math.h>
#include <stdint.h>

// Problem shapes (fixed per reference)
#define N_NODES 20000
#define N_EDGES 40000
#define H 64
#define F_ATOM 62
#define F_BOND 6
#define BGRAPH 512
#define HH 4096          // H*H
#define E_PAD 40064      // 313 * 128, padded edge count for 128-row MMA tiles

// ---------------- scratch (device globals; no allocs allowed) ----------------
__device__ float g_h[N_NODES * H];                    // node state (fp32)
__device__ float g_msg[N_NODES * H];                  // per-step message accumulator
__device__ float g_act[N_NODES * H];                  // atom activation
__device__ __nv_bfloat16 g_mlpb[E_PAD * H];           // edge MLP features (bf16)
__device__ __nv_bfloat16 g_EwB[HH * H];               // B operand: EwB[n=j*64+i][m] = Ew[m][i*64+j]
__device__ __nv_bfloat16 g_Abf[(size_t)E_PAD * HH];   // per-edge matrices, transposed: At[e][j*64+i], bf16
__device__ float g_gsum[BGRAPH * H];                  // graph segment sums

// ---------------- math helpers ----------------
__device__ __forceinline__ float selu_f(float x) {
    const float alpha = 1.6732632423543772f;
    const float scale = 1.0507009873554805f;
    return x > 0.f ? scale * x : scale * alpha * expm1f(x);
}

__device__ __forceinline__ void mma_bf16_16816(float c[4], const uint32_t a[4],
                                               const uint32_t b0, const uint32_t b1) {
    asm volatile(
        "mma.sync.aligned.m16n8k16.row.col.f32.bf16.bf16.f32 "
        "{%0,%1,%2,%3}, {%4,%5,%6,%7}, {%8,%9}, {%0,%1,%2,%3};"
        : "+f"(c[0]), "+f"(c[1]), "+f"(c[2]), "+f"(c[3])
        : "r"(a[0]), "r"(a[1]), "r"(a[2]), "r"(a[3]), "r"(b0), "r"(b1));
}

__device__ __forceinline__ void ldsm_x4(uint32_t r[4], uint32_t saddr) {
    asm volatile("ldmatrix.sync.aligned.m8n8.x4.shared.b16 {%0,%1,%2,%3}, [%4];"
                 : "=r"(r[0]), "=r"(r[1]), "=r"(r[2]), "=r"(r[3]) : "r"(saddr));
}

// ---------------- fused prep: pad h, edge MLP, build B, zero msg ----------------
#define PREP_PAD_BLKS 5000                  // N_NODES*H/256
#define PREP_MLP_BLKS (E_PAD / 4)           // 10016
#define PREP_B_BLKS 1024                    // H*HH/256
#define PREP_ZERO_BLKS 5000                 // N_NODES*H/256
#define PREP_GRID (PREP_PAD_BLKS + PREP_MLP_BLKS + PREP_B_BLKS + PREP_ZERO_BLKS)

__global__ void k_prep(const float* __restrict__ nf, const float* __restrict__ ef,
                       const float* __restrict__ Wm, const float* __restrict__ bm,
                       const float* __restrict__ Ew) {
    int b = blockIdx.x;
    int tid = threadIdx.x;
    if (b < PREP_PAD_BLKS) {
        int idx = b * 256 + tid;
        int n = idx >> 6, c = idx & 63;
        g_h[idx] = (c < F_ATOM) ? nf[n * F_ATOM + c] : 0.f;
    } else if (b < PREP_PAD_BLKS + PREP_MLP_BLKS) {
        __shared__ float s_ef[4][F_BOND];
        int eb = b - PREP_PAD_BLKS;
        int sub = tid >> 6, i = tid & 63;
        int e = eb * 4 + sub;
        if (i < F_BOND) s_ef[sub][i] = (e < N_EDGES) ? ef[e * F_BOND + i] : 0.f;
        __syncthreads();
        float v = bm[i];
#pragma unroll
        for (int f = 0; f < F_BOND; f++) v += s_ef[sub][f] * Wm[f * H + i];
        v = fmaxf(v, 0.f);
        if (e >= N_EDGES) v = 0.f;
        g_mlpb[e * H + i] = __float2bfloat16_rn(v);
    } else if (b < PREP_PAD_BLKS + PREP_MLP_BLKS + PREP_B_BLKS) {
        int o = (b - PREP_PAD_BLKS - PREP_MLP_BLKS) * 256 + tid;
        int n = o >> 6, m = o & 63;
        int j = n >> 6, i = n & 63;
        g_EwB[o] = __float2bfloat16_rn(Ew[(m << 12) + (i << 6) + j]);
    } else {
        int idx = (b - PREP_PAD_BLKS - PREP_MLP_BLKS - PREP_B_BLKS) * 256 + tid;
        g_msg[idx] = 0.f;
    }
}

// A = mlp[E,64] @ EwB^T via mma.sync bf16 (HMMA) with ldmatrix fragment loads
// and a smem-staged fully-coalesced epilogue. (R7-proven, unchanged.)
#define SROW 36   // padded row (u32 words); 144B -> 16B-aligned rows
#define CROW 68   // staged-C row (u32 words); 272B -> 16B-aligned rows
__global__ void __launch_bounds__(256) k_gemmA_mma() {
    __shared__ __align__(16) uint32_t smem_all[2 * 128 * SROW];  // 36 KB
    uint32_t* sA = smem_all;
    uint32_t* sB = smem_all + 128 * SROW;
    int tid = threadIdx.x;
    int m0 = blockIdx.y * 128;
    int n0 = blockIdx.x * 128;

    const uint4* gA = (const uint4*)(g_mlpb + (size_t)m0 * H);
    const uint4* gB = (const uint4*)(g_EwB + (size_t)n0 * H);
#pragma unroll
    for (int it = 0; it < 4; it++) {
        int idx = it * 256 + tid;
        int row = idx >> 3, c = idx & 7;
        *(uint4*)&sA[row * SROW + c * 4] = gA[idx];
        *(uint4*)&sB[row * SROW + c * 4] = gB[idx];
    }
    __syncthreads();

    int wid = tid >> 5, lane = tid & 31;
    int g = lane >> 2, tg = lane & 3;
    int wm = (wid & 1) * 64;
    int wn = (wid >> 1) * 32;

    int lrow = (lane & 7) + ((lane >> 3) & 1) * 8;
    int lcol = (lane >> 4) * 4;

    uint32_t sA_u32 = (uint32_t)__cvta_generic_to_shared(sA);
    uint32_t sB_u32 = (uint32_t)__cvta_generic_to_shared(sB);

    float c[4][4][4] = {};
#pragma unroll
    for (int kk = 0; kk < 4; kk++) {
        uint32_t a[4][4];
#pragma unroll
        for (int mi = 0; mi < 4; mi++) {
            uint32_t addr = sA_u32 + ((wm + mi * 16 + lrow) * SROW + kk * 8 + lcol) * 4;
            ldsm_x4(a[mi], addr);
        }
        uint32_t bq[2][4];
#pragma unroll
        for (int nh = 0; nh < 2; nh++) {
            uint32_t addr = sB_u32 + ((wn + nh * 16 + lrow) * SROW + kk * 8 + lcol) * 4;
            ldsm_x4(bq[nh], addr);
        }
#pragma unroll
        for (int mi = 0; mi < 4; mi++) {
            mma_bf16_16816(c[mi][0], a[mi], bq[0][0], bq[0][2]);
            mma_bf16_16816(c[mi][1], a[mi], bq[0][1], bq[0][3]);
            mma_bf16_16816(c[mi][2], a[mi], bq[1][0], bq[1][2]);
            mma_bf16_16816(c[mi][3], a[mi], bq[1][1], bq[1][3]);
        }
    }

    __syncthreads();
    uint32_t* sC = smem_all;
#pragma unroll
    for (int mi = 0; mi < 4; mi++) {
        int r0 = wm + mi * 16 + g;
#pragma unroll
        for (int ni = 0; ni < 4; ni++) {
            int cw = (wn >> 1) + ni * 4 + tg;
            __nv_bfloat162 lo = __float22bfloat162_rn(make_float2(c[mi][ni][0], c[mi][ni][1]));
            __nv_bfloat162 hi = __float22bfloat162_rn(make_float2(c[mi][ni][2], c[mi][ni][3]));
            sC[r0 * CROW + cw] = *(uint32_t*)&lo;
            sC[(r0 + 8) * CROW + cw] = *(uint32_t*)&hi;
        }
    }
    __syncthreads();

    int half = lane >> 4;
    int seg = lane & 15;
#pragma unroll
    for (int r = 0; r < 8; r++) {
        int row = wid * 16 + 2 * r + half;
        uint4 v = *(uint4*)&sC[row * CROW + seg * 4];
        *(uint4*)(g_Abf + (size_t)(m0 + row) * HH + n0 + seg * 8) = v;
    }
}

// edge pass v2: 1 edge per warp, LDG.128 streaming loads, shfl reduction. (R10-proven.)
__global__ void __launch_bounds__(256) k_edge(const int* __restrict__ dom,
                                              const int* __restrict__ rng) {
    __shared__ float s_hj[8][64];
    int tid = threadIdx.x;
    int sub = tid >> 5, lane = tid & 31;
    int e = blockIdx.x * 8 + sub;
    int r = rng[e];
    float2 hv = *(const float2*)(g_h + r * H + 2 * lane);
    s_hj[sub][2 * lane] = hv.x;
    s_hj[sub][2 * lane + 1] = hv.y;
    __syncwarp();

    int iseg = lane & 7, jsub = lane >> 3;
    const uint4* Ae = (const uint4*)(g_Abf + (size_t)e * HH);
    float acc[8] = {};
#pragma unroll
    for (int s = 0; s < 16; s++) {
        int j = s * 4 + jsub;
        uint4 raw = __ldcs(&Ae[s * 32 + lane]);
        float hjv = s_hj[sub][j];
        const uint32_t w[4] = {raw.x, raw.y, raw.z, raw.w};
#pragma unroll
        for (int q = 0; q < 4; q++) {
            __nv_bfloat162 a2 = *reinterpret_cast<const __nv_bfloat162*>(&w[q]);
            float2 f = __bfloat1622float2(a2);
            acc[2 * q + 0] = fmaf(f.x, hjv, acc[2 * q + 0]);
            acc[2 * q + 1] = fmaf(f.y, hjv, acc[2 * q + 1]);
        }
    }
#pragma unroll
    for (int k = 0; k < 8; k++) {
        acc[k] += __shfl_xor_sync(0xFFFFFFFF, acc[k], 8);
        acc[k] += __shfl_xor_sync(0xFFFFFFFF, acc[k], 16);
    }
    int d = dom[e];
    int k0 = jsub * 2;
    atomicAdd(&g_msg[d * H + iseg * 8 + k0 + 0], acc[k0 + 0]);
    atomicAdd(&g_msg[d * H + iseg * 8 + k0 + 1], acc[k0 + 1]);
}

// h = selu(msg @ Wu + bu + h); resets msg. 16 nodes/block, 4 nodes/thread:
// one Wu load feeds 4 independent FMAs (ILP 4, Wu loads /4).
__global__ void __launch_bounds__(256) k_update(const float* __restrict__ Wu,
                                                const float* __restrict__ bu) {
    __shared__ float s_m[16][64];
    int tid = threadIdx.x;
    int i = tid & 63, sub = tid >> 6;        // sub 0..3 -> nodes sub*4..sub*4+3
    int n0 = blockIdx.x * 16;
#pragma unroll
    for (int it = 0; it < 4; it++) {
        int idx = it * 256 + tid;            // 0..1023
        int row = idx >> 6, col = idx & 63;
        int gi = (n0 + row) * H + col;
        s_m[row][col] = g_msg[gi];
        g_msg[gi] = 0.f;
    }
    __syncthreads();
    float b = bu[i];
    float acc[4] = {b, b, b, b};
#pragma unroll 16
    for (int k = 0; k < 64; k++) {
        float w = Wu[k * H + i];
#pragma unroll
        for (int u = 0; u < 4; u++) acc[u] = fmaf(s_m[sub * 4 + u][k], w, acc[u]);
    }
#pragma unroll
    for (int u = 0; u < 4; u++) {
        int idx = (n0 + sub * 4 + u) * H + i;
        g_h[idx] = selu_f(acc[u] + g_h[idx]);
    }
}

// act = selu((h @ Wae + bae) @ WR + bR); 16 nodes/block, 4/thread; zeroes gsum.
__global__ void __launch_bounds__(256) k_embed(const float* __restrict__ Wae,
                                               const float* __restrict__ bae,
                                               const float* __restrict__ WR,
                                               const float* __restrict__ bR) {
    __shared__ float s_h[16][64];
    __shared__ float s_ae[16][64];
    int tid = threadIdx.x;
    if (blockIdx.x < 128) g_gsum[blockIdx.x * 256 + tid] = 0.f;
    int i = tid & 63, sub = tid >> 6;
    int n0 = blockIdx.x * 16;
#pragma unroll
    for (int it = 0; it < 4; it++) {
        int idx = it * 256 + tid;
        int row = idx >> 6, col = idx & 63;
        s_h[row][col] = g_h[(n0 + row) * H + col];
    }
    __syncthreads();
    float b1 = bae[i];
    float ae[4] = {b1, b1, b1, b1};
#pragma unroll 16
    for (int k = 0; k < 64; k++) {
        float w = Wae[k * H + i];
#pragma unroll
        for (int u = 0; u < 4; u++) ae[u] = fmaf(s_h[sub * 4 + u][k], w, ae[u]);
    }
#pragma unroll
    for (int u = 0; u < 4; u++) s_ae[sub * 4 + u][i] = ae[u];
    __syncthreads();
    float b2 = bR[i];
    float acc[4] = {b2, b2, b2, b2};
#pragma unroll 16
    for (int k = 0; k < 64; k++) {
        float w = WR[k * H + i];
#pragma unroll
        for (int u = 0; u < 4; u++) acc[u] = fmaf(s_ae[sub * 4 + u][k], w, acc[u]);
    }
#pragma unroll
    for (int u = 0; u < 4; u++)
        g_act[(n0 + sub * 4 + u) * H + i] = selu_f(acc[u]);
}

// segment-sum act over graph_id
__global__ void k_graphsum(const int* __restrict__ gid) {
    int idx = blockIdx.x * blockDim.x + threadIdx.x;
    if (idx >= N_NODES * H) return;
    int n = idx >> 6, i = idx & 63;
    atomicAdd(&g_gsum[gid[n] * H + i], g_act[idx]);
}

// out[b] = relu(tanh(gsum[b]) @ Wmlp + bmlp) @ Wout + bout
__global__ void k_readout(const float* __restrict__ Wmlp, const float* __restrict__ bmlp,
                          const float* __restrict__ Wout, const float* __restrict__ bout,
                          float* __restrict__ out) {
    __shared__ float s_ge[64];
    __shared__ float s_red[64];
    int b = blockIdx.x, i = threadIdx.x;
    s_ge[i] = tanhf(g_gsum[b * H + i]);
    __syncthreads();
    float acc = bmlp[i];
#pragma unroll 8
    for (int k = 0; k < 64; k++) acc = fmaf(s_ge[k], Wmlp[k * H + i], acc);
    float p = fmaxf(acc, 0.f) * Wout[i];
    s_red[i] = p;
    __syncthreads();
#pragma unroll
    for (int s = 32; s > 0; s >>= 1) {
        if (i < s) s_red[i] += s_red[i + s];
        __syncthreads();
    }
    if (i == 0) out[b] = s_red[0] + bout[0];
}

extern "C" void kernel_launch(void* const* d_in, const int* in_sizes, int n_in,
                              void* d_out, int out_size) {
    const float* node_features = (const float*)d_in[0];
    const float* edge_features = (const float*)d_in[1];
    const int*   edge_domain   = (const int*)d_in[2];
    const int*   edge_range    = (const int*)d_in[3];
    const int*   graph_id      = (const int*)d_in[4];
    const float* Wm   = (const float*)d_in[5];
    const float* bm   = (const float*)d_in[6];
    const float* Ew   = (const float*)d_in[7];
    const float* Wu0  = (const float*)d_in[8];
    const float* bu0  = (const float*)d_in[9];
    const float* Wu1  = (const float*)d_in[10];
    const float* bu1  = (const float*)d_in[11];
    const float* Wae  = (const float*)d_in[12];
    const float* bae  = (const float*)d_in[13];
    const float* WR   = (const float*)d_in[14];
    const float* bR   = (const float*)d_in[15];
    const float* Wmlp = (const float*)d_in[16];
    const float* bmlp = (const float*)d_in[17];
    const float* Wout = (const float*)d_in[18];
    const float* bout = (const float*)d_in[19];
    float* out = (float*)d_out;

    // fused prep: pad h, edge MLP, build B operand, zero g_msg
    k_prep<<<PREP_GRID, 256>>>(node_features, edge_features, Wm, bm, Ew);

    // A = mlp @ EwB^T on tensor cores (bf16 HMMA, fp32 accumulate, bf16 out)
    dim3 gA(HH / 128, E_PAD / 128);
    k_gemmA_mma<<<gA, 256>>>();

    // message passing steps
    const float* Wus[2] = {Wu0, Wu1};
    const float* bus[2] = {bu0, bu1};
    for (int t = 0; t < 2; t++) {
        k_edge<<<N_EDGES / 8, 256>>>(edge_domain, edge_range);
        k_update<<<N_NODES / 16, 256>>>(Wus[t], bus[t]);  // also re-zeroes g_msg
    }

    // readout
    k_embed<<<N_NODES / 16, 256>>>(Wae, bae, WR, bR);     // also zeroes g_gsum
    k_graphsum<<<(N_NODES * H + 255) / 256, 256>>>(graph_id);
    k_readout<<<BGRAPH, 64>>>(Wmlp, bmlp, Wout, bout, out);
}

// round 13
// speedup vs baseline: 1.3960x; 1.0581x over previous
#include <cuda_runtime.h>
#include <cuda_bf16.h>
#include <math.h>
#include <stdint.h>

// Problem shapes (fixed per reference)
#define N_NODES 20000
#define N_EDGES 40000
#define H 64
#define F_ATOM 62
#define F_BOND 6
#define BGRAPH 512
#define HH 4096          // H*H
#define E_PAD 40064      // 313 * 128, padded edge count for 128-row MMA tiles

// ---------------- scratch (device globals; no allocs allowed) ----------------
__device__ __align__(256) float g_h[N_NODES * H];                    // node state (fp32)
__device__ __align__(256) float g_msg[N_NODES * H];                  // per-step message accumulator
__device__ __align__(256) float g_act[N_NODES * H];                  // atom activation
__device__ __align__(256) __nv_bfloat16 g_mlpb[E_PAD * H];           // edge MLP features (bf16)
__device__ __align__(256) __nv_bfloat16 g_EwB[HH * H];               // B operand: EwB[n=j*64+i][m] = Ew[m][i*64+j]
__device__ __align__(256) __nv_bfloat16 g_Abf[(size_t)E_PAD * HH];   // per-edge matrices, transposed: At[e][j*64+i], bf16
__device__ __align__(256) float g_gsum[BGRAPH * H];                  // graph segment sums

// ---------------- math helpers ----------------
__device__ __forceinline__ float selu_f(float x) {
    const float alpha = 1.6732632423543772f;
    const float scale = 1.0507009873554805f;
    return x > 0.f ? scale * x : scale * alpha * expm1f(x);
}

__device__ __forceinline__ void mma_bf16_16816(float c[4], const uint32_t a[4],
                                               const uint32_t b0, const uint32_t b1) {
    asm volatile(
        "mma.sync.aligned.m16n8k16.row.col.f32.bf16.bf16.f32 "
        "{%0,%1,%2,%3}, {%4,%5,%6,%7}, {%8,%9}, {%0,%1,%2,%3};"
        : "+f"(c[0]), "+f"(c[1]), "+f"(c[2]), "+f"(c[3])
        : "r"(a[0]), "r"(a[1]), "r"(a[2]), "r"(a[3]), "r"(b0), "r"(b1));
}

__device__ __forceinline__ void ldsm_x4(uint32_t r[4], uint32_t saddr) {
    asm volatile("ldmatrix.sync.aligned.m8n8.x4.shared.b16 {%0,%1,%2,%3}, [%4];"
                 : "=r"(r[0]), "=r"(r[1]), "=r"(r[2]), "=r"(r[3]) : "r"(saddr));
}

// ---------------- fused prep: pad h, edge MLP, build B, zero msg ----------------
#define PREP_PAD_BLKS 5000                  // N_NODES*H/256
#define PREP_MLP_BLKS (E_PAD / 4)           // 10016
#define PREP_B_BLKS 1024                    // H*HH/256
#define PREP_ZERO_BLKS 5000                 // N_NODES*H/256
#define PREP_GRID (PREP_PAD_BLKS + PREP_MLP_BLKS + PREP_B_BLKS + PREP_ZERO_BLKS)

__global__ void k_prep(const float* __restrict__ nf, const float* __restrict__ ef,
                       const float* __restrict__ Wm, const float* __restrict__ bm,
                       const float* __restrict__ Ew) {
    int b = blockIdx.x;
    int tid = threadIdx.x;
    if (b < PREP_PAD_BLKS) {
        int idx = b * 256 + tid;
        int n = idx >> 6, c = idx & 63;
        g_h[idx] = (c < F_ATOM) ? nf[n * F_ATOM + c] : 0.f;
    } else if (b < PREP_PAD_BLKS + PREP_MLP_BLKS) {
        __shared__ float s_ef[4][F_BOND];
        int eb = b - PREP_PAD_BLKS;
        int sub = tid >> 6, i = tid & 63;
        int e = eb * 4 + sub;
        if (i < F_BOND) s_ef[sub][i] = (e < N_EDGES) ? ef[e * F_BOND + i] : 0.f;
        __syncthreads();
        float v = bm[i];
#pragma unroll
        for (int f = 0; f < F_BOND; f++) v += s_ef[sub][f] * Wm[f * H + i];
        v = fmaxf(v, 0.f);
        if (e >= N_EDGES) v = 0.f;
        g_mlpb[e * H + i] = __float2bfloat16_rn(v);
    } else if (b < PREP_PAD_BLKS + PREP_MLP_BLKS + PREP_B_BLKS) {
        int o = (b - PREP_PAD_BLKS - PREP_MLP_BLKS) * 256 + tid;
        int n = o >> 6, m = o & 63;
        int j = n >> 6, i = n & 63;
        g_EwB[o] = __float2bfloat16_rn(Ew[(m << 12) + (i << 6) + j]);
    } else {
        int idx = (b - PREP_PAD_BLKS - PREP_MLP_BLKS - PREP_B_BLKS) * 256 + tid;
        g_msg[idx] = 0.f;
    }
}

// A = mlp[E,64] @ EwB^T via mma.sync bf16 (HMMA) with ldmatrix fragment loads
// and a smem-staged fully-coalesced epilogue. (R7-proven, unchanged.)
#define SROW 36   // padded row (u32 words); 144B -> 16B-aligned rows
#define CROW 68   // staged-C row (u32 words); 272B -> 16B-aligned rows
__global__ void __launch_bounds__(256) k_gemmA_mma() {
    __shared__ __align__(16) uint32_t smem_all[2 * 128 * SROW];  // 36 KB
    uint32_t* sA = smem_all;
    uint32_t* sB = smem_all + 128 * SROW;
    int tid = threadIdx.x;
    int m0 = blockIdx.y * 128;
    int n0 = blockIdx.x * 128;

    const uint4* gA = (const uint4*)(g_mlpb + (size_t)m0 * H);
    const uint4* gB = (const uint4*)(g_EwB + (size_t)n0 * H);
#pragma unroll
    for (int it = 0; it < 4; it++) {
        int idx = it * 256 + tid;
        int row = idx >> 3, c = idx & 7;
        *(uint4*)&sA[row * SROW + c * 4] = gA[idx];
        *(uint4*)&sB[row * SROW + c * 4] = gB[idx];
    }
    __syncthreads();

    int wid = tid >> 5, lane = tid & 31;
    int g = lane >> 2, tg = lane & 3;
    int wm = (wid & 1) * 64;
    int wn = (wid >> 1) * 32;

    int lrow = (lane & 7) + ((lane >> 3) & 1) * 8;
    int lcol = (lane >> 4) * 4;

    uint32_t sA_u32 = (uint32_t)__cvta_generic_to_shared(sA);
    uint32_t sB_u32 = (uint32_t)__cvta_generic_to_shared(sB);

    float c[4][4][4] = {};
#pragma unroll
    for (int kk = 0; kk < 4; kk++) {
        uint32_t a[4][4];
#pragma unroll
        for (int mi = 0; mi < 4; mi++) {
            uint32_t addr = sA_u32 + ((wm + mi * 16 + lrow) * SROW + kk * 8 + lcol) * 4;
            ldsm_x4(a[mi], addr);
        }
        uint32_t bq[2][4];
#pragma unroll
        for (int nh = 0; nh < 2; nh++) {
            uint32_t addr = sB_u32 + ((wn + nh * 16 + lrow) * SROW + kk * 8 + lcol) * 4;
            ldsm_x4(bq[nh], addr);
        }
#pragma unroll
        for (int mi = 0; mi < 4; mi++) {
            mma_bf16_16816(c[mi][0], a[mi], bq[0][0], bq[0][2]);
            mma_bf16_16816(c[mi][1], a[mi], bq[0][1], bq[0][3]);
            mma_bf16_16816(c[mi][2], a[mi], bq[1][0], bq[1][2]);
            mma_bf16_16816(c[mi][3], a[mi], bq[1][1], bq[1][3]);
        }
    }

    __syncthreads();
    uint32_t* sC = smem_all;
#pragma unroll
    for (int mi = 0; mi < 4; mi++) {
        int r0 = wm + mi * 16 + g;
#pragma unroll
        for (int ni = 0; ni < 4; ni++) {
            int cw = (wn >> 1) + ni * 4 + tg;
            __nv_bfloat162 lo = __float22bfloat162_rn(make_float2(c[mi][ni][0], c[mi][ni][1]));
            __nv_bfloat162 hi = __float22bfloat162_rn(make_float2(c[mi][ni][2], c[mi][ni][3]));
            sC[r0 * CROW + cw] = *(uint32_t*)&lo;
            sC[(r0 + 8) * CROW + cw] = *(uint32_t*)&hi;
        }
    }
    __syncthreads();

    int half = lane >> 4;
    int seg = lane & 15;
#pragma unroll
    for (int r = 0; r < 8; r++) {
        int row = wid * 16 + 2 * r + half;
        uint4 v = *(uint4*)&sC[row * CROW + seg * 4];
        *(uint4*)(g_Abf + (size_t)(m0 + row) * HH + n0 + seg * 8) = v;
    }
}

// edge pass v2: 1 edge per warp, LDG.128 streaming loads, shfl reduction. (R10-proven.)
__global__ void __launch_bounds__(256) k_edge(const int* __restrict__ dom,
                                              const int* __restrict__ rng) {
    __shared__ float s_hj[8][64];
    int tid = threadIdx.x;
    int sub = tid >> 5, lane = tid & 31;
    int e = blockIdx.x * 8 + sub;
    int r = rng[e];
    float2 hv = *(const float2*)(g_h + r * H + 2 * lane);
    s_hj[sub][2 * lane] = hv.x;
    s_hj[sub][2 * lane + 1] = hv.y;
    __syncwarp();

    int iseg = lane & 7, jsub = lane >> 3;
    const uint4* Ae = (const uint4*)(g_Abf + (size_t)e * HH);
    float acc[8] = {};
#pragma unroll
    for (int s = 0; s < 16; s++) {
        int j = s * 4 + jsub;
        uint4 raw = __ldcs(&Ae[s * 32 + lane]);
        float hjv = s_hj[sub][j];
        const uint32_t w[4] = {raw.x, raw.y, raw.z, raw.w};
#pragma unroll
        for (int q = 0; q < 4; q++) {
            __nv_bfloat162 a2 = *reinterpret_cast<const __nv_bfloat162*>(&w[q]);
            float2 f = __bfloat1622float2(a2);
            acc[2 * q + 0] = fmaf(f.x, hjv, acc[2 * q + 0]);
            acc[2 * q + 1] = fmaf(f.y, hjv, acc[2 * q + 1]);
        }
    }
#pragma unroll
    for (int k = 0; k < 8; k++) {
        acc[k] += __shfl_xor_sync(0xFFFFFFFF, acc[k], 8);
        acc[k] += __shfl_xor_sync(0xFFFFFFFF, acc[k], 16);
    }
    int d = dom[e];
    int k0 = jsub * 2;
    atomicAdd(&g_msg[d * H + iseg * 8 + k0 + 0], acc[k0 + 0]);
    atomicAdd(&g_msg[d * H + iseg * 8 + k0 + 1], acc[k0 + 1]);
}

// h = selu(msg @ Wu + bu + h); resets msg. 32 nodes/block, 8 nodes/thread,
// k in chunks of 4 via LDS.128 broadcast: per 32 FMAs only 4 LDG + 8 LDS.128.
__global__ void __launch_bounds__(256) k_update(const float* __restrict__ Wu,
                                                const float* __restrict__ bu) {
    __shared__ __align__(16) float s_m[32][64];
    int tid = threadIdx.x;
    int i = tid & 63, sub = tid >> 6;        // sub 0..3 -> nodes sub*8..sub*8+7
    int n0 = blockIdx.x * 32;
    // load msg (float4) + zero it
    float4* gm = (float4*)(g_msg + n0 * H);
    float4* sm4 = (float4*)s_m;
    const float4 z4 = make_float4(0.f, 0.f, 0.f, 0.f);
#pragma unroll
    for (int it = 0; it < 2; it++) {
        int idx = it * 256 + tid;            // 0..511 float4s
        sm4[idx] = gm[idx];
        gm[idx] = z4;
    }
    __syncthreads();
    float b = bu[i];
    float acc[8] = {b, b, b, b, b, b, b, b};
#pragma unroll 4
    for (int kc = 0; kc < 16; kc++) {        // k chunk = kc*4
        int k = kc * 4;
        float w0 = Wu[(k + 0) * H + i];
        float w1 = Wu[(k + 1) * H + i];
        float w2 = Wu[(k + 2) * H + i];
        float w3 = Wu[(k + 3) * H + i];
#pragma unroll
        for (int u = 0; u < 8; u++) {
            float4 m4 = *(const float4*)&s_m[sub * 8 + u][k];   // broadcast LDS.128
            acc[u] = fmaf(m4.x, w0, acc[u]);
            acc[u] = fmaf(m4.y, w1, acc[u]);
            acc[u] = fmaf(m4.z, w2, acc[u]);
            acc[u] = fmaf(m4.w, w3, acc[u]);
        }
    }
#pragma unroll
    for (int u = 0; u < 8; u++) {
        int idx = (n0 + sub * 8 + u) * H + i;
        g_h[idx] = selu_f(acc[u] + g_h[idx]);
    }
}

// act = selu((h @ Wae + bae) @ WR + bR); 32 nodes/block, 8/thread; zeroes gsum.
__global__ void __launch_bounds__(256) k_embed(const float* __restrict__ Wae,
                                               const float* __restrict__ bae,
                                               const float* __restrict__ WR,
                                               const float* __restrict__ bR) {
    __shared__ __align__(16) float s_h[32][64];
    __shared__ __align__(16) float s_ae[32][64];
    int tid = threadIdx.x;
    if (blockIdx.x < 128) g_gsum[blockIdx.x * 256 + tid] = 0.f;
    int i = tid & 63, sub = tid >> 6;
    int n0 = blockIdx.x * 32;
    const float4* gh = (const float4*)(g_h + n0 * H);
    float4* sh4 = (float4*)s_h;
#pragma unroll
    for (int it = 0; it < 2; it++) {
        int idx = it * 256 + tid;
        sh4[idx] = gh[idx];
    }
    __syncthreads();
    float b1 = bae[i];
    float ae[8] = {b1, b1, b1, b1, b1, b1, b1, b1};
#pragma unroll 4
    for (int kc = 0; kc < 16; kc++) {
        int k = kc * 4;
        float w0 = Wae[(k + 0) * H + i];
        float w1 = Wae[(k + 1) * H + i];
        float w2 = Wae[(k + 2) * H + i];
        float w3 = Wae[(k + 3) * H + i];
#pragma unroll
        for (int u = 0; u < 8; u++) {
            float4 m4 = *(const float4*)&s_h[sub * 8 + u][k];
            ae[u] = fmaf(m4.x, w0, ae[u]);
            ae[u] = fmaf(m4.y, w1, ae[u]);
            ae[u] = fmaf(m4.z, w2, ae[u]);
            ae[u] = fmaf(m4.w, w3, ae[u]);
        }
    }
#pragma unroll
    for (int u = 0; u < 8; u++) s_ae[sub * 8 + u][i] = ae[u];
    __syncthreads();
    float b2 = bR[i];
    float acc[8] = {b2, b2, b2, b2, b2, b2, b2, b2};
#pragma unroll 4
    for (int kc = 0; kc < 16; kc++) {
        int k = kc * 4;
        float w0 = WR[(k + 0) * H + i];
        float w1 = WR[(k + 1) * H + i];
        float w2 = WR[(k + 2) * H + i];
        float w3 = WR[(k + 3) * H + i];
#pragma unroll
        for (int u = 0; u < 8; u++) {
            float4 m4 = *(const float4*)&s_ae[sub * 8 + u][k];
            acc[u] = fmaf(m4.x, w0, acc[u]);
            acc[u] = fmaf(m4.y, w1, acc[u]);
            acc[u] = fmaf(m4.z, w2, acc[u]);
            acc[u] = fmaf(m4.w, w3, acc[u]);
        }
    }
#pragma unroll
    for (int u = 0; u < 8; u++)
        g_act[(n0 + sub * 8 + u) * H + i] = selu_f(acc[u]);
}

// segment-sum act over graph_id
__global__ void k_graphsum(const int* __restrict__ gid) {
    int idx = blockIdx.x * blockDim.x + threadIdx.x;
    if (idx >= N_NODES * H) return;
    int n = idx >> 6, i = idx & 63;
    atomicAdd(&g_gsum[gid[n] * H + i], g_act[idx]);
}

// out[b] = relu(tanh(gsum[b]) @ Wmlp + bmlp) @ Wout + bout
__global__ void k_readout(const float* __restrict__ Wmlp, const float* __restrict__ bmlp,
                          const float* __restrict__ Wout, const float* __restrict__ bout,
                          float* __restrict__ out) {
    __shared__ float s_ge[64];
    __shared__ float s_red[64];
    int b = blockIdx.x, i = threadIdx.x;
    s_ge[i] = tanhf(g_gsum[b * H + i]);
    __syncthreads();
    float acc = bmlp[i];
#pragma unroll 8
    for (int k = 0; k < 64; k++) acc = fmaf(s_ge[k], Wmlp[k * H + i], acc);
    float p = fmaxf(acc, 0.f) * Wout[i];
    s_red[i] = p;
    __syncthreads();
#pragma unroll
    for (int s = 32; s > 0; s >>= 1) {
        if (i < s) s_red[i] += s_red[i + s];
        __syncthreads();
    }
    if (i == 0) out[b] = s_red[0] + bout[0];
}

extern "C" void kernel_launch(void* const* d_in, const int* in_sizes, int n_in,
                              void* d_out, int out_size) {
    const float* node_features = (const float*)d_in[0];
    const float* edge_features = (const float*)d_in[1];
    const int*   edge_domain   = (const int*)d_in[2];
    const int*   edge_range    = (const int*)d_in[3];
    const int*   graph_id      = (const int*)d_in[4];
    const float* Wm   = (const float*)d_in[5];
    const float* bm   = (const float*)d_in[6];
    const float* Ew   = (const float*)d_in[7];
    const float* Wu0  = (const float*)d_in[8];
    const float* bu0  = (const float*)d_in[9];
    const float* Wu1  = (const float*)d_in[10];
    const float* bu1  = (const float*)d_in[11];
    const float* Wae  = (const float*)d_in[12];
    const float* bae  = (const float*)d_in[13];
    const float* WR   = (const float*)d_in[14];
    const float* bR   = (const float*)d_in[15];
    const float* Wmlp = (const float*)d_in[16];
    const float* bmlp = (const float*)d_in[17];
    const float* Wout = (const float*)d_in[18];
    const float* bout = (const float*)d_in[19];
    float* out = (float*)d_out;

    // fused prep: pad h, edge MLP, build B operand, zero g_msg
    k_prep<<<PREP_GRID, 256>>>(node_features, edge_features, Wm, bm, Ew);

    // A = mlp @ EwB^T on tensor cores (bf16 HMMA, fp32 accumulate, bf16 out)
    dim3 gA(HH / 128, E_PAD / 128);
    k_gemmA_mma<<<gA, 256>>>();

    // message passing steps
    const float* Wus[2] = {Wu0, Wu1};
    const float* bus[2] = {bu0, bu1};
    for (int t = 0; t < 2; t++) {
        k_edge<<<N_EDGES / 8, 256>>>(edge_domain, edge_range);
        k_update<<<N_NODES / 32, 256>>>(Wus[t], bus[t]);  // also re-zeroes g_msg
    }

    // readout
    k_embed<<<N_NODES / 32, 256>>>(Wae, bae, WR, bR);     // also zeroes g_gsum
    k_graphsum<<<(N_NODES * H + 255) / 256, 256>>>(graph_id);
    k_readout<<<BGRAPH, 64>>>(Wmlp, bmlp, Wout, bout, out);
}

// round 14
// speedup vs baseline: 1.4148x; 1.0135x over previous
#include <cuda_runtime.h>
#include <cuda_bf16.h>
#include <math.h>
#include <stdint.h>

// Problem shapes (fixed per reference)
#define N_NODES 20000
#define N_EDGES 40000
#define H 64
#define F_ATOM 62
#define F_BOND 6
#define BGRAPH 512
#define HH 4096          // H*H
#define E_PAD 40064      // 313 * 128, padded edge count for 128-row tiles

// ---------------- scratch (device globals; no allocs allowed) ----------------
__device__ __align__(256) float g_h[N_NODES * H];            // node state (fp32)
__device__ __align__(256) float g_msg[N_NODES * H];          // per-step message accumulator
__device__ __align__(256) float g_act[N_NODES * H];          // atom activation
__device__ __align__(256) __nv_bfloat16 g_mlpb[E_PAD * H];   // edge MLP features (bf16)
__device__ __align__(256) __nv_bfloat16 g_Ewb[H * HH];       // Ew cast to bf16 (same layout)
__device__ __align__(256) float g_gsum[BGRAPH * H];          // graph segment sums

// ---------------- math helpers ----------------
__device__ __forceinline__ float selu_f(float x) {
    const float alpha = 1.6732632423543772f;
    const float scale = 1.0507009873554805f;
    return x > 0.f ? scale * x : scale * alpha * expm1f(x);
}

__device__ __forceinline__ void mma_bf16_16816(float c[4], const uint32_t a[4],
                                               const uint32_t b0, const uint32_t b1) {
    asm volatile(
        "mma.sync.aligned.m16n8k16.row.col.f32.bf16.bf16.f32 "
        "{%0,%1,%2,%3}, {%4,%5,%6,%7}, {%8,%9}, {%0,%1,%2,%3};"
        : "+f"(c[0]), "+f"(c[1]), "+f"(c[2]), "+f"(c[3])
        : "r"(a[0]), "r"(a[1]), "r"(a[2]), "r"(a[3]), "r"(b0), "r"(b1));
}

__device__ __forceinline__ void ldsm_x4(uint32_t r[4], uint32_t saddr) {
    asm volatile("ldmatrix.sync.aligned.m8n8.x4.shared.b16 {%0,%1,%2,%3}, [%4];"
                 : "=r"(r[0]), "=r"(r[1]), "=r"(r[2]), "=r"(r[3]) : "r"(saddr));
}

// ---------------- fused prep: pad h, edge MLP, cast Ew, zero msg ----------------
#define PREP_PAD_BLKS 5000                  // N_NODES*H/256
#define PREP_MLP_BLKS (E_PAD / 4)           // 10016
#define PREP_B_BLKS 1024                    // H*HH/256
#define PREP_ZERO_BLKS 5000                 // N_NODES*H/256
#define PREP_GRID (PREP_PAD_BLKS + PREP_MLP_BLKS + PREP_B_BLKS + PREP_ZERO_BLKS)

__global__ void k_prep(const float* __restrict__ nf, const float* __restrict__ ef,
                       const float* __restrict__ Wm, const float* __restrict__ bm,
                       const float* __restrict__ Ew) {
    int b = blockIdx.x;
    int tid = threadIdx.x;
    if (b < PREP_PAD_BLKS) {
        int idx = b * 256 + tid;
        int n = idx >> 6, c = idx & 63;
        g_h[idx] = (c < F_ATOM) ? nf[n * F_ATOM + c] : 0.f;
    } else if (b < PREP_PAD_BLKS + PREP_MLP_BLKS) {
        __shared__ float s_ef[4][F_BOND];
        int eb = b - PREP_PAD_BLKS;
        int sub = tid >> 6, i = tid & 63;
        int e = eb * 4 + sub;
        if (i < F_BOND) s_ef[sub][i] = (e < N_EDGES) ? ef[e * F_BOND + i] : 0.f;
        __syncthreads();
        float v = bm[i];
#pragma unroll
        for (int f = 0; f < F_BOND; f++) v += s_ef[sub][f] * Wm[f * H + i];
        v = fmaxf(v, 0.f);
        if (e >= N_EDGES) v = 0.f;
        g_mlpb[e * H + i] = __float2bfloat16_rn(v);
    } else if (b < PREP_PAD_BLKS + PREP_MLP_BLKS + PREP_B_BLKS) {
        int o = (b - PREP_PAD_BLKS - PREP_MLP_BLKS) * 256 + tid;
        g_Ewb[o] = __float2bfloat16_rn(Ew[o]);
    } else {
        int idx = (b - PREP_PAD_BLKS - PREP_MLP_BLKS - PREP_B_BLKS) * 256 + tid;
        g_msg[idx] = 0.f;
    }
}

// ============================================================================
// Fused message step (no A materialization):
//   msg[e,i] += sum_{m,j} (mlp[e,m]*h[rng[e],j]) * Ew[m, i*64+j]
// GEMM [128 edges x 64] with K=4096, K-chunks of 64 (one m per chunk).
// A-operand o[e, j] = mlp[e,m]*hj[e,j] formed in smem per chunk (fp32 product,
// single bf16 rounding). B-operand = Ew chunk (m*4096, reshaped 64x64,
// row=i? no: rows (m,i) pairs... Ew[m][i*64+j]: tile rows i, cols j = the
// proven [n][k] orientation for mma.sync col-major B).
// 256 threads, 8 warps (4x2): warp tile 32 rows x 32 cols. 313 CTAs.
// ============================================================================
__global__ void __launch_bounds__(256, 2) k_medge(const int* __restrict__ dom,
                                                  const int* __restrict__ rng) {
    __shared__ __align__(16) __nv_bfloat16 s_mlpT[64 * 128];  // [m][e], 16 KB
    __shared__ __align__(16) uint32_t s_o[128 * 36];          // o tile, 144B pitch, 18 KB
    __shared__ __align__(16) uint32_t s_ew[64 * 36];          // Ew chunk, 144B pitch, 9 KB
    __shared__ int s_dom[128];
    int tid = threadIdx.x;
    int e0 = blockIdx.x * 128;

    // setup: mlp tile transposed into smem ([m][e] for conflict-free scalar reads)
    {
        int e = tid >> 1, half = tid & 1;
        const uint4* src = (const uint4*)(g_mlpb + (size_t)(e0 + e) * H + half * 32);
        uint4 v[4];
        v[0] = src[0]; v[1] = src[1]; v[2] = src[2]; v[3] = src[3];
        const __nv_bfloat16* bv = (const __nv_bfloat16*)v;
#pragma unroll
        for (int k = 0; k < 32; k++)
            s_mlpT[(half * 32 + k) * 128 + e] = bv[k];
    }
    if (tid < 128) {
        int ge = e0 + tid;
        s_dom[tid] = (ge < N_EDGES) ? dom[ge] : 0;
    }

    // gather hj into registers: thread owns rows q, q+32, q+64, q+96; j-octet jo
    int q = tid & 31, jo = tid >> 5;
    float hj[4][8];
#pragma unroll
    for (int u = 0; u < 4; u++) {
        int r = q + u * 32;
        int ge = e0 + r;
        int rr = (ge < N_EDGES) ? __ldg(&rng[ge]) : 0;
        float4 a = *(const float4*)(g_h + rr * H + jo * 8);
        float4 b = *(const float4*)(g_h + rr * H + jo * 8 + 4);
        hj[u][0] = a.x; hj[u][1] = a.y; hj[u][2] = a.z; hj[u][3] = a.w;
        hj[u][4] = b.x; hj[u][5] = b.y; hj[u][6] = b.z; hj[u][7] = b.w;
    }

    // prefetch Ew chunk 0 (512 uint4 per chunk; 2 per thread)
    uint4 pf0, pf1;
    {
        const uint4* src = (const uint4*)g_Ewb;
        pf0 = src[2 * tid];
        pf1 = src[2 * tid + 1];
    }
    __syncthreads();   // s_mlpT, s_dom ready

    int lane = tid & 31, wid = tid >> 5;
    int g_ = lane >> 2, tg = lane & 3;
    int wm = (wid & 3) * 32;    // warp rows
    int wn = (wid >> 2) * 32;   // warp cols
    int lrow = (lane & 7) + ((lane >> 3) & 1) * 8;
    int lcol = (lane >> 4) * 4;

    uint32_t so_u32 = (uint32_t)__cvta_generic_to_shared(s_o);
    uint32_t sew_u32 = (uint32_t)__cvta_generic_to_shared(s_ew);

    float c[2][4][4] = {};

    for (int m = 0; m < 64; m++) {
        // store prefetched Ew chunk
        {
            int i0 = 2 * tid;
            *(uint4*)&s_ew[(i0 >> 3) * 36 + (i0 & 7) * 4] = pf0;
            int i1 = 2 * tid + 1;
            *(uint4*)&s_ew[(i1 >> 3) * 36 + (i1 & 7) * 4] = pf1;
        }
        // form o chunk: o[r, j] = mlp[r, m] * hj[r, j]  (fp32 product, bf16 round)
#pragma unroll
        for (int u = 0; u < 4; u++) {
            int r = q + u * 32;
            float a = __bfloat162float(s_mlpT[m * 128 + r]);
            uint32_t pk[4];
#pragma unroll
            for (int p = 0; p < 4; p++) {
                __nv_bfloat162 b2 = __float22bfloat162_rn(
                    make_float2(a * hj[u][2 * p], a * hj[u][2 * p + 1]));
                pk[p] = *(uint32_t*)&b2;
            }
            *(uint4*)&s_o[r * 36 + jo * 4] = make_uint4(pk[0], pk[1], pk[2], pk[3]);
        }
        __syncthreads();

        // prefetch next chunk during MMA
        if (m < 63) {
            const uint4* src = (const uint4*)(g_Ewb + (size_t)(m + 1) * HH);
            pf0 = src[2 * tid];
            pf1 = src[2 * tid + 1];
        }

        // MMA: K=64 in 4 k16 steps
#pragma unroll
        for (int kk = 0; kk < 4; kk++) {
            uint32_t a[2][4];
#pragma unroll
            for (int mi = 0; mi < 2; mi++) {
                uint32_t addr = so_u32 + ((wm + mi * 16 + lrow) * 36 + kk * 8 + lcol) * 4;
                ldsm_x4(a[mi], addr);
            }
            uint32_t bq[2][4];
#pragma unroll
            for (int nh = 0; nh < 2; nh++) {
                uint32_t addr = sew_u32 + ((wn + nh * 16 + lrow) * 36 + kk * 8 + lcol) * 4;
                ldsm_x4(bq[nh], addr);
            }
#pragma unroll
            for (int mi = 0; mi < 2; mi++) {
                mma_bf16_16816(c[mi][0], a[mi], bq[0][0], bq[0][2]);
                mma_bf16_16816(c[mi][1], a[mi], bq[0][1], bq[0][3]);
                mma_bf16_16816(c[mi][2], a[mi], bq[1][0], bq[1][2]);
                mma_bf16_16816(c[mi][3], a[mi], bq[1][1], bq[1][3]);
            }
        }
        __syncthreads();   // all ldsm done before next chunk overwrites
    }

    // flush accumulated messages (padded edges: mlp=0 -> o=0 -> c=0, dom=0 safe)
#pragma unroll
    for (int mi = 0; mi < 2; mi++) {
#pragma unroll
        for (int ni = 0; ni < 4; ni++) {
#pragma unroll
            for (int v = 0; v < 4; v++) {
                int r = wm + mi * 16 + g_ + ((v >> 1) & 1) * 8;
                int col = wn + ni * 8 + tg * 2 + (v & 1);
                atomicAdd(&g_msg[s_dom[r] * H + col], c[mi][ni][v]);
            }
        }
    }
}

// h = selu(msg @ Wu + bu + h); resets msg. 32 nodes/block, 8 nodes/thread. (R13-proven.)
__global__ void __launch_bounds__(256) k_update(const float* __restrict__ Wu,
                                                const float* __restrict__ bu) {
    __shared__ __align__(16) float s_m[32][64];
    int tid = threadIdx.x;
    int i = tid & 63, sub = tid >> 6;
    int n0 = blockIdx.x * 32;
    float4* gm = (float4*)(g_msg + n0 * H);
    float4* sm4 = (float4*)s_m;
    const float4 z4 = make_float4(0.f, 0.f, 0.f, 0.f);
#pragma unroll
    for (int it = 0; it < 2; it++) {
        int idx = it * 256 + tid;
        sm4[idx] = gm[idx];
        gm[idx] = z4;
    }
    __syncthreads();
    float b = bu[i];
    float acc[8] = {b, b, b, b, b, b, b, b};
#pragma unroll 4
    for (int kc = 0; kc < 16; kc++) {
        int k = kc * 4;
        float w0 = Wu[(k + 0) * H + i];
        float w1 = Wu[(k + 1) * H + i];
        float w2 = Wu[(k + 2) * H + i];
        float w3 = Wu[(k + 3) * H + i];
#pragma unroll
        for (int u = 0; u < 8; u++) {
            float4 m4 = *(const float4*)&s_m[sub * 8 + u][k];
            acc[u] = fmaf(m4.x, w0, acc[u]);
            acc[u] = fmaf(m4.y, w1, acc[u]);
            acc[u] = fmaf(m4.z, w2, acc[u]);
            acc[u] = fmaf(m4.w, w3, acc[u]);
        }
    }
#pragma unroll
    for (int u = 0; u < 8; u++) {
        int idx = (n0 + sub * 8 + u) * H + i;
        g_h[idx] = selu_f(acc[u] + g_h[idx]);
    }
}

// act = selu((h @ Wae + bae) @ WR + bR); 32 nodes/block, 8/thread; zeroes gsum. (R13-proven.)
__global__ void __launch_bounds__(256) k_embed(const float* __restrict__ Wae,
                                               const float* __restrict__ bae,
                                               const float* __restrict__ WR,
                                               const float* __restrict__ bR) {
    __shared__ __align__(16) float s_h[32][64];
    __shared__ __align__(16) float s_ae[32][64];
    int tid = threadIdx.x;
    if (blockIdx.x < 128) g_gsum[blockIdx.x * 256 + tid] = 0.f;
    int i = tid & 63, sub = tid >> 6;
    int n0 = blockIdx.x * 32;
    const float4* gh = (const float4*)(g_h + n0 * H);
    float4* sh4 = (float4*)s_h;
#pragma unroll
    for (int it = 0; it < 2; it++) {
        int idx = it * 256 + tid;
        sh4[idx] = gh[idx];
    }
    __syncthreads();
    float b1 = bae[i];
    float ae[8] = {b1, b1, b1, b1, b1, b1, b1, b1};
#pragma unroll 4
    for (int kc = 0; kc < 16; kc++) {
        int k = kc * 4;
        float w0 = Wae[(k + 0) * H + i];
        float w1 = Wae[(k + 1) * H + i];
        float w2 = Wae[(k + 2) * H + i];
        float w3 = Wae[(k + 3) * H + i];
#pragma unroll
        for (int u = 0; u < 8; u++) {
            float4 m4 = *(const float4*)&s_h[sub * 8 + u][k];
            ae[u] = fmaf(m4.x, w0, ae[u]);
            ae[u] = fmaf(m4.y, w1, ae[u]);
            ae[u] = fmaf(m4.z, w2, ae[u]);
            ae[u] = fmaf(m4.w, w3, ae[u]);
        }
    }
#pragma unroll
    for (int u = 0; u < 8; u++) s_ae[sub * 8 + u][i] = ae[u];
    __syncthreads();
    float b2 = bR[i];
    float acc[8] = {b2, b2, b2, b2, b2, b2, b2, b2};
#pragma unroll 4
    for (int kc = 0; kc < 16; kc++) {
        int k = kc * 4;
        float w0 = WR[(k + 0) * H + i];
        float w1 = WR[(k + 1) * H + i];
        float w2 = WR[(k + 2) * H + i];
        float w3 = WR[(k + 3) * H + i];
#pragma unroll
        for (int u = 0; u < 8; u++) {
            float4 m4 = *(const float4*)&s_ae[sub * 8 + u][k];
            acc[u] = fmaf(m4.x, w0, acc[u]);
            acc[u] = fmaf(m4.y, w1, acc[u]);
            acc[u] = fmaf(m4.z, w2, acc[u]);
            acc[u] = fmaf(m4.w, w3, acc[u]);
        }
    }
#pragma unroll
    for (int u = 0; u < 8; u++)
        g_act[(n0 + sub * 8 + u) * H + i] = selu_f(acc[u]);
}

// segment-sum act over graph_id
__global__ void k_graphsum(const int* __restrict__ gid) {
    int idx = blockIdx.x * blockDim.x + threadIdx.x;
    if (idx >= N_NODES * H) return;
    int n = idx >> 6, i = idx & 63;
    atomicAdd(&g_gsum[gid[n] * H + i], g_act[idx]);
}

// out[b] = relu(tanh(gsum[b]) @ Wmlp + bmlp) @ Wout + bout
__global__ void k_readout(const float* __restrict__ Wmlp, const float* __restrict__ bmlp,
                          const float* __restrict__ Wout, const float* __restrict__ bout,
                          float* __restrict__ out) {
    __shared__ float s_ge[64];
    __shared__ float s_red[64];
    int b = blockIdx.x, i = threadIdx.x;
    s_ge[i] = tanhf(g_gsum[b * H + i]);
    __syncthreads();
    float acc = bmlp[i];
#pragma unroll 8
    for (int k = 0; k < 64; k++) acc = fmaf(s_ge[k], Wmlp[k * H + i], acc);
    float p = fmaxf(acc, 0.f) * Wout[i];
    s_red[i] = p;
    __syncthreads();
#pragma unroll
    for (int s = 32; s > 0; s >>= 1) {
        if (i < s) s_red[i] += s_red[i + s];
        __syncthreads();
    }
    if (i == 0) out[b] = s_red[0] + bout[0];
}

extern "C" void kernel_launch(void* const* d_in, const int* in_sizes, int n_in,
                              void* d_out, int out_size) {
    const float* node_features = (const float*)d_in[0];
    const float* edge_features = (const float*)d_in[1];
    const int*   edge_domain   = (const int*)d_in[2];
    const int*   edge_range    = (const int*)d_in[3];
    const int*   graph_id      = (const int*)d_in[4];
    const float* Wm   = (const float*)d_in[5];
    const float* bm   = (const float*)d_in[6];
    const float* Ew   = (const float*)d_in[7];
    const float* Wu0  = (const float*)d_in[8];
    const float* bu0  = (const float*)d_in[9];
    const float* Wu1  = (const float*)d_in[10];
    const float* bu1  = (const float*)d_in[11];
    const float* Wae  = (const float*)d_in[12];
    const float* bae  = (const float*)d_in[13];
    const float* WR   = (const float*)d_in[14];
    const float* bR   = (const float*)d_in[15];
    const float* Wmlp = (const float*)d_in[16];
    const float* bmlp = (const float*)d_in[17];
    const float* Wout = (const float*)d_in[18];
    const float* bout = (const float*)d_in[19];
    float* out = (float*)d_out;

    // fused prep: pad h, edge MLP, cast Ew to bf16, zero g_msg
    k_prep<<<PREP_GRID, 256>>>(node_features, edge_features, Wm, bm, Ew);

    // message passing steps: fused on-the-fly GEMM (no A materialization)
    const float* Wus[2] = {Wu0, Wu1};
    const float* bus[2] = {bu0, bu1};
    for (int t = 0; t < 2; t++) {
        k_medge<<<E_PAD / 128, 256>>>(edge_domain, edge_range);
        k_update<<<N_NODES / 32, 256>>>(Wus[t], bus[t]);  // also re-zeroes g_msg
    }

    // readout
    k_embed<<<N_NODES / 32, 256>>>(Wae, bae, WR, bR);     // also zeroes g_gsum
    k_graphsum<<<(N_NODES * H + 255) / 256, 256>>>(graph_id);
    k_readout<<<BGRAPH, 64>>>(Wmlp, bmlp, Wout, bout, out);
}

// round 15
// speedup vs baseline: 1.5756x; 1.1136x over previous
#include <cuda_runtime.h>
#include <cuda_bf16.h>
#include <math.h>
#include <stdint.h>

// Problem shapes (fixed per reference)
#define N_NODES 20000
#define N_EDGES 40000
#define H 64
#define F_ATOM 62
#define F_BOND 6
#define BGRAPH 512
#define HH 4096          // H*H
#define E_PAD 40064      // 313 * 128, padded edge count for 128-row tiles
#define KSEG 2           // K-range split across CTAs (m-chunks per CTA = 64/KSEG)

// ---------------- scratch (device globals; no allocs allowed) ----------------
__device__ __align__(256) float g_h[N_NODES * H];            // node state (fp32)
__device__ __align__(256) float g_msg[N_NODES * H];          // per-step message accumulator
__device__ __align__(256) float g_act[N_NODES * H];          // atom activation
__device__ __align__(256) __nv_bfloat16 g_mlpb[E_PAD * H];   // edge MLP features (bf16)
__device__ __align__(256) __nv_bfloat16 g_Ewb[H * HH];       // Ew cast to bf16 (same layout)
__device__ __align__(256) float g_gsum[BGRAPH * H];          // graph segment sums

// ---------------- math helpers ----------------
__device__ __forceinline__ float selu_f(float x) {
    const float alpha = 1.6732632423543772f;
    const float scale = 1.0507009873554805f;
    return x > 0.f ? scale * x : scale * alpha * expm1f(x);
}

__device__ __forceinline__ void mma_bf16_16816(float c[4], const uint32_t a[4],
                                               const uint32_t b0, const uint32_t b1) {
    asm volatile(
        "mma.sync.aligned.m16n8k16.row.col.f32.bf16.bf16.f32 "
        "{%0,%1,%2,%3}, {%4,%5,%6,%7}, {%8,%9}, {%0,%1,%2,%3};"
        : "+f"(c[0]), "+f"(c[1]), "+f"(c[2]), "+f"(c[3])
        : "r"(a[0]), "r"(a[1]), "r"(a[2]), "r"(a[3]), "r"(b0), "r"(b1));
}

__device__ __forceinline__ void ldsm_x4(uint32_t r[4], uint32_t saddr) {
    asm volatile("ldmatrix.sync.aligned.m8n8.x4.shared.b16 {%0,%1,%2,%3}, [%4];"
                 : "=r"(r[0]), "=r"(r[1]), "=r"(r[2]), "=r"(r[3]) : "r"(saddr));
}

// ---------------- fused prep: pad h, edge MLP, cast Ew, zero msg ----------------
#define PREP_PAD_BLKS 5000                  // N_NODES*H/256
#define PREP_MLP_BLKS (E_PAD / 4)           // 10016
#define PREP_B_BLKS 1024                    // H*HH/256
#define PREP_ZERO_BLKS 5000                 // N_NODES*H/256
#define PREP_GRID (PREP_PAD_BLKS + PREP_MLP_BLKS + PREP_B_BLKS + PREP_ZERO_BLKS)

__global__ void k_prep(const float* __restrict__ nf, const float* __restrict__ ef,
                       const float* __restrict__ Wm, const float* __restrict__ bm,
                       const float* __restrict__ Ew) {
    int b = blockIdx.x;
    int tid = threadIdx.x;
    if (b < PREP_PAD_BLKS) {
        int idx = b * 256 + tid;
        int n = idx >> 6, c = idx & 63;
        g_h[idx] = (c < F_ATOM) ? nf[n * F_ATOM + c] : 0.f;
    } else if (b < PREP_PAD_BLKS + PREP_MLP_BLKS) {
        __shared__ float s_ef[4][F_BOND];
        int eb = b - PREP_PAD_BLKS;
        int sub = tid >> 6, i = tid & 63;
        int e = eb * 4 + sub;
        if (i < F_BOND) s_ef[sub][i] = (e < N_EDGES) ? ef[e * F_BOND + i] : 0.f;
        __syncthreads();
        float v = bm[i];
#pragma unroll
        for (int f = 0; f < F_BOND; f++) v += s_ef[sub][f] * Wm[f * H + i];
        v = fmaxf(v, 0.f);
        if (e >= N_EDGES) v = 0.f;
        g_mlpb[e * H + i] = __float2bfloat16_rn(v);
    } else if (b < PREP_PAD_BLKS + PREP_MLP_BLKS + PREP_B_BLKS) {
        int o = (b - PREP_PAD_BLKS - PREP_MLP_BLKS) * 256 + tid;
        g_Ewb[o] = __float2bfloat16_rn(Ew[o]);
    } else {
        int idx = (b - PREP_PAD_BLKS - PREP_MLP_BLKS - PREP_B_BLKS) * 256 + tid;
        g_msg[idx] = 0.f;
    }
}

// ============================================================================
// Fused message step (no A materialization), K-split across KSEG CTAs:
//   msg[e,i] += sum_{m in seg, j} (mlp[e,m]*h[rng[e],j]) * Ew[m, i*64+j]
// Grid (E_PAD/128, KSEG); CTA (bx, seg) covers 128 edges x 32 m-chunks.
// Per chunk: form o[e,j]=mlp[e,m]*hj[e,j] in smem (bf16), MMA vs Ew chunk
// (reshaped 64x64, [n][k] orientation), accumulate fp32; flush via atomicAdd.
// ============================================================================
__global__ void __launch_bounds__(256, 2) k_medge(const int* __restrict__ dom,
                                                  const int* __restrict__ rng) {
    __shared__ __align__(16) __nv_bfloat16 s_mlpT[64 * 128];  // [m][e], 16 KB
    __shared__ __align__(16) uint32_t s_o[128 * 36];          // o tile, 144B pitch, 18 KB
    __shared__ __align__(16) uint32_t s_ew[64 * 36];          // Ew chunk, 144B pitch, 9 KB
    __shared__ int s_dom[128];
    int tid = threadIdx.x;
    int e0 = blockIdx.x * 128;
    int m0 = blockIdx.y * (64 / KSEG);
    const int MCH = 64 / KSEG;

    // setup: mlp tile transposed into smem ([m][e] for conflict-free scalar reads)
    {
        int e = tid >> 1, half = tid & 1;
        const uint4* src = (const uint4*)(g_mlpb + (size_t)(e0 + e) * H + half * 32);
        uint4 v[4];
        v[0] = src[0]; v[1] = src[1]; v[2] = src[2]; v[3] = src[3];
        const __nv_bfloat16* bv = (const __nv_bfloat16*)v;
#pragma unroll
        for (int k = 0; k < 32; k++)
            s_mlpT[(half * 32 + k) * 128 + e] = bv[k];
    }
    if (tid < 128) {
        int ge = e0 + tid;
        s_dom[tid] = (ge < N_EDGES) ? dom[ge] : 0;
    }

    // gather hj into registers: thread owns rows q, q+32, q+64, q+96; j-octet jo
    int q = tid & 31, jo = tid >> 5;
    float hj[4][8];
#pragma unroll
    for (int u = 0; u < 4; u++) {
        int r = q + u * 32;
        int ge = e0 + r;
        int rr = (ge < N_EDGES) ? __ldg(&rng[ge]) : 0;
        float4 a = *(const float4*)(g_h + rr * H + jo * 8);
        float4 b = *(const float4*)(g_h + rr * H + jo * 8 + 4);
        hj[u][0] = a.x; hj[u][1] = a.y; hj[u][2] = a.z; hj[u][3] = a.w;
        hj[u][4] = b.x; hj[u][5] = b.y; hj[u][6] = b.z; hj[u][7] = b.w;
    }

    // prefetch first Ew chunk of this segment (512 uint4 per chunk; 2 per thread)
    uint4 pf0, pf1;
    {
        const uint4* src = (const uint4*)(g_Ewb + (size_t)m0 * HH);
        pf0 = src[2 * tid];
        pf1 = src[2 * tid + 1];
    }
    __syncthreads();   // s_mlpT, s_dom ready

    int lane = tid & 31, wid = tid >> 5;
    int g_ = lane >> 2, tg = lane & 3;
    int wm = (wid & 3) * 32;    // warp rows
    int wn = (wid >> 2) * 32;   // warp cols
    int lrow = (lane & 7) + ((lane >> 3) & 1) * 8;
    int lcol = (lane >> 4) * 4;

    uint32_t so_u32 = (uint32_t)__cvta_generic_to_shared(s_o);
    uint32_t sew_u32 = (uint32_t)__cvta_generic_to_shared(s_ew);

    float c[2][4][4] = {};

    for (int mc = 0; mc < MCH; mc++) {
        int m = m0 + mc;
        // store prefetched Ew chunk
        {
            int i0 = 2 * tid;
            *(uint4*)&s_ew[(i0 >> 3) * 36 + (i0 & 7) * 4] = pf0;
            int i1 = 2 * tid + 1;
            *(uint4*)&s_ew[(i1 >> 3) * 36 + (i1 & 7) * 4] = pf1;
        }
        // form o chunk: o[r, j] = mlp[r, m] * hj[r, j]  (fp32 product, bf16 round)
#pragma unroll
        for (int u = 0; u < 4; u++) {
            int r = q + u * 32;
            float a = __bfloat162float(s_mlpT[m * 128 + r]);
            uint32_t pk[4];
#pragma unroll
            for (int p = 0; p < 4; p++) {
                __nv_bfloat162 b2 = __float22bfloat162_rn(
                    make_float2(a * hj[u][2 * p], a * hj[u][2 * p + 1]));
                pk[p] = *(uint32_t*)&b2;
            }
            *(uint4*)&s_o[r * 36 + jo * 4] = make_uint4(pk[0], pk[1], pk[2], pk[3]);
        }
        __syncthreads();

        // prefetch next chunk during MMA
        if (mc < MCH - 1) {
            const uint4* src = (const uint4*)(g_Ewb + (size_t)(m + 1) * HH);
            pf0 = src[2 * tid];
            pf1 = src[2 * tid + 1];
        }

        // MMA: K=64 in 4 k16 steps
#pragma unroll
        for (int kk = 0; kk < 4; kk++) {
            uint32_t a[2][4];
#pragma unroll
            for (int mi = 0; mi < 2; mi++) {
                uint32_t addr = so_u32 + ((wm + mi * 16 + lrow) * 36 + kk * 8 + lcol) * 4;
                ldsm_x4(a[mi], addr);
            }
            uint32_t bq[2][4];
#pragma unroll
            for (int nh = 0; nh < 2; nh++) {
                uint32_t addr = sew_u32 + ((wn + nh * 16 + lrow) * 36 + kk * 8 + lcol) * 4;
                ldsm_x4(bq[nh], addr);
            }
#pragma unroll
            for (int mi = 0; mi < 2; mi++) {
                mma_bf16_16816(c[mi][0], a[mi], bq[0][0], bq[0][2]);
                mma_bf16_16816(c[mi][1], a[mi], bq[0][1], bq[0][3]);
                mma_bf16_16816(c[mi][2], a[mi], bq[1][0], bq[1][2]);
                mma_bf16_16816(c[mi][3], a[mi], bq[1][1], bq[1][3]);
            }
        }
        __syncthreads();   // all ldsm done before next chunk overwrites
    }

    // flush accumulated messages (padded edges: mlp=0 -> o=0 -> c=0, dom=0 safe)
#pragma unroll
    for (int mi = 0; mi < 2; mi++) {
#pragma unroll
        for (int ni = 0; ni < 4; ni++) {
#pragma unroll
            for (int v = 0; v < 4; v++) {
                int r = wm + mi * 16 + g_ + ((v >> 1) & 1) * 8;
                int col = wn + ni * 8 + tg * 2 + (v & 1);
                atomicAdd(&g_msg[s_dom[r] * H + col], c[mi][ni][v]);
            }
        }
    }
}

// h = selu(msg @ Wu + bu + h); resets msg. 32 nodes/block, 8 nodes/thread. (R13-proven.)
__global__ void __launch_bounds__(256) k_update(const float* __restrict__ Wu,
                                                const float* __restrict__ bu) {
    __shared__ __align__(16) float s_m[32][64];
    int tid = threadIdx.x;
    int i = tid & 63, sub = tid >> 6;
    int n0 = blockIdx.x * 32;
    float4* gm = (float4*)(g_msg + n0 * H);
    float4* sm4 = (float4*)s_m;
    const float4 z4 = make_float4(0.f, 0.f, 0.f, 0.f);
#pragma unroll
    for (int it = 0; it < 2; it++) {
        int idx = it * 256 + tid;
        sm4[idx] = gm[idx];
        gm[idx] = z4;
    }
    __syncthreads();
    float b = bu[i];
    float acc[8] = {b, b, b, b, b, b, b, b};
#pragma unroll 4
    for (int kc = 0; kc < 16; kc++) {
        int k = kc * 4;
        float w0 = Wu[(k + 0) * H + i];
        float w1 = Wu[(k + 1) * H + i];
        float w2 = Wu[(k + 2) * H + i];
        float w3 = Wu[(k + 3) * H + i];
#pragma unroll
        for (int u = 0; u < 8; u++) {
            float4 m4 = *(const float4*)&s_m[sub * 8 + u][k];
            acc[u] = fmaf(m4.x, w0, acc[u]);
            acc[u] = fmaf(m4.y, w1, acc[u]);
            acc[u] = fmaf(m4.z, w2, acc[u]);
            acc[u] = fmaf(m4.w, w3, acc[u]);
        }
    }
#pragma unroll
    for (int u = 0; u < 8; u++) {
        int idx = (n0 + sub * 8 + u) * H + i;
        g_h[idx] = selu_f(acc[u] + g_h[idx]);
    }
}

// act = selu((h @ Wae + bae) @ WR + bR); 32 nodes/block, 8/thread; zeroes gsum. (R13-proven.)
__global__ void __launch_bounds__(256) k_embed(const float* __restrict__ Wae,
                                               const float* __restrict__ bae,
                                               const float* __restrict__ WR,
                                               const float* __restrict__ bR) {
    __shared__ __align__(16) float s_h[32][64];
    __shared__ __align__(16) float s_ae[32][64];
    int tid = threadIdx.x;
    if (blockIdx.x < 128) g_gsum[blockIdx.x * 256 + tid] = 0.f;
    int i = tid & 63, sub = tid >> 6;
    int n0 = blockIdx.x * 32;
    const float4* gh = (const float4*)(g_h + n0 * H);
    float4* sh4 = (float4*)s_h;
#pragma unroll
    for (int it = 0; it < 2; it++) {
        int idx = it * 256 + tid;
        sh4[idx] = gh[idx];
    }
    __syncthreads();
    float b1 = bae[i];
    float ae[8] = {b1, b1, b1, b1, b1, b1, b1, b1};
#pragma unroll 4
    for (int kc = 0; kc < 16; kc++) {
        int k = kc * 4;
        float w0 = Wae[(k + 0) * H + i];
        float w1 = Wae[(k + 1) * H + i];
        float w2 = Wae[(k + 2) * H + i];
        float w3 = Wae[(k + 3) * H + i];
#pragma unroll
        for (int u = 0; u < 8; u++) {
            float4 m4 = *(const float4*)&s_h[sub * 8 + u][k];
            ae[u] = fmaf(m4.x, w0, ae[u]);
            ae[u] = fmaf(m4.y, w1, ae[u]);
            ae[u] = fmaf(m4.z, w2, ae[u]);
            ae[u] = fmaf(m4.w, w3, ae[u]);
        }
    }
#pragma unroll
    for (int u = 0; u < 8; u++) s_ae[sub * 8 + u][i] = ae[u];
    __syncthreads();
    float b2 = bR[i];
    float acc[8] = {b2, b2, b2, b2, b2, b2, b2, b2};
#pragma unroll 4
    for (int kc = 0; kc < 16; kc++) {
        int k = kc * 4;
        float w0 = WR[(k + 0) * H + i];
        float w1 = WR[(k + 1) * H + i];
        float w2 = WR[(k + 2) * H + i];
        float w3 = WR[(k + 3) * H + i];
#pragma unroll
        for (int u = 0; u < 8; u++) {
            float4 m4 = *(const float4*)&s_ae[sub * 8 + u][k];
            acc[u] = fmaf(m4.x, w0, acc[u]);
            acc[u] = fmaf(m4.y, w1, acc[u]);
            acc[u] = fmaf(m4.z, w2, acc[u]);
            acc[u] = fmaf(m4.w, w3, acc[u]);
        }
    }
#pragma unroll
    for (int u = 0; u < 8; u++)
        g_act[(n0 + sub * 8 + u) * H + i] = selu_f(acc[u]);
}

// segment-sum act over graph_id
__global__ void k_graphsum(const int* __restrict__ gid) {
    int idx = blockIdx.x * blockDim.x + threadIdx.x;
    if (idx >= N_NODES * H) return;
    int n = idx >> 6, i = idx & 63;
    atomicAdd(&g_gsum[gid[n] * H + i], g_act[idx]);
}

// out[b] = relu(tanh(gsum[b]) @ Wmlp + bmlp) @ Wout + bout
__global__ void k_readout(const float* __restrict__ Wmlp, const float* __restrict__ bmlp,
                          const float* __restrict__ Wout, const float* __restrict__ bout,
                          float* __restrict__ out) {
    __shared__ float s_ge[64];
    __shared__ float s_red[64];
    int b = blockIdx.x, i = threadIdx.x;
    s_ge[i] = tanhf(g_gsum[b * H + i]);
    __syncthreads();
    float acc = bmlp[i];
#pragma unroll 8
    for (int k = 0; k < 64; k++) acc = fmaf(s_ge[k], Wmlp[k * H + i], acc);
    float p = fmaxf(acc, 0.f) * Wout[i];
    s_red[i] = p;
    __syncthreads();
#pragma unroll
    for (int s = 32; s > 0; s >>= 1) {
        if (i < s) s_red[i] += s_red[i + s];
        __syncthreads();
    }
    if (i == 0) out[b] = s_red[0] + bout[0];
}

extern "C" void kernel_launch(void* const* d_in, const int* in_sizes, int n_in,
                              void* d_out, int out_size) {
    const float* node_features = (const float*)d_in[0];
    const float* edge_features = (const float*)d_in[1];
    const int*   edge_domain   = (const int*)d_in[2];
    const int*   edge_range    = (const int*)d_in[3];
    const int*   graph_id      = (const int*)d_in[4];
    const float* Wm   = (const float*)d_in[5];
    const float* bm   = (const float*)d_in[6];
    const float* Ew   = (const float*)d_in[7];
    const float* Wu0  = (const float*)d_in[8];
    const float* bu0  = (const float*)d_in[9];
    const float* Wu1  = (const float*)d_in[10];
    const float* bu1  = (const float*)d_in[11];
    const float* Wae  = (const float*)d_in[12];
    const float* bae  = (const float*)d_in[13];
    const float* WR   = (const float*)d_in[14];
    const float* bR   = (const float*)d_in[15];
    const float* Wmlp = (const float*)d_in[16];
    const float* bmlp = (const float*)d_in[17];
    const float* Wout = (const float*)d_in[18];
    const float* bout = (const float*)d_in[19];
    float* out = (float*)d_out;

    // fused prep: pad h, edge MLP, cast Ew to bf16, zero g_msg
    k_prep<<<PREP_GRID, 256>>>(node_features, edge_features, Wm, bm, Ew);

    // message passing steps: fused on-the-fly GEMM, K-split across KSEG CTAs
    const float* Wus[2] = {Wu0, Wu1};
    const float* bus[2] = {bu0, bu1};
    dim3 gM(E_PAD / 128, KSEG);
    for (int t = 0; t < 2; t++) {
        k_medge<<<gM, 256>>>(edge_domain, edge_range);
        k_update<<<N_NODES / 32, 256>>>(Wus[t], bus[t]);  // also re-zeroes g_msg
    }

    // readout
    k_embed<<<N_NODES / 32, 256>>>(Wae, bae, WR, bR);     // also zeroes g_gsum
    k_graphsum<<<(N_NODES * H + 255) / 256, 256>>>(graph_id);
    k_readout<<<BGRAPH, 64>>>(Wmlp, bmlp, Wout, bout, out);
}

// round 16
// speedup vs baseline: 1.8372x; 1.1660x over previous
#include <cuda_runtime.h>
#include <cuda_bf16.h>
#include <math.h>
#include <stdint.h>

// Problem shapes (fixed per reference)
#define N_NODES 20000
#define N_EDGES 40000
#define H 64
#define F_ATOM 62
#define F_BOND 6
#define BGRAPH 512
#define HH 4096          // H*H
#define E_PAD 40064      // 313 * 128, padded edge count for 128-row tiles
#define KSEG 2           // K-range split across CTAs (m-chunks per CTA = 64/KSEG)
#define MCH (64 / KSEG)

// ---------------- scratch (device globals; no allocs allowed) ----------------
__device__ __align__(256) float g_h[N_NODES * H];            // node state (fp32)
__device__ __align__(256) float g_msg[N_NODES * H];          // per-step message accumulator
__device__ __align__(256) float g_act[N_NODES * H];          // atom activation
__device__ __align__(256) __nv_bfloat16 g_mlpb[E_PAD * H];   // edge MLP features (bf16)
__device__ __align__(256) __nv_bfloat16 g_Ewb[H * HH];       // Ew cast to bf16 (same layout)
__device__ __align__(256) float g_gsum[BGRAPH * H];          // graph segment sums

// ---------------- math helpers ----------------
__device__ __forceinline__ float selu_f(float x) {
    const float alpha = 1.6732632423543772f;
    const float scale = 1.0507009873554805f;
    return x > 0.f ? scale * x : scale * alpha * expm1f(x);
}

__device__ __forceinline__ void mma_bf16_16816(float c[4], const uint32_t a[4],
                                               const uint32_t b0, const uint32_t b1) {
    asm volatile(
        "mma.sync.aligned.m16n8k16.row.col.f32.bf16.bf16.f32 "
        "{%0,%1,%2,%3}, {%4,%5,%6,%7}, {%8,%9}, {%0,%1,%2,%3};"
        : "+f"(c[0]), "+f"(c[1]), "+f"(c[2]), "+f"(c[3])
        : "r"(a[0]), "r"(a[1]), "r"(a[2]), "r"(a[3]), "r"(b0), "r"(b1));
}

__device__ __forceinline__ void ldsm_x4(uint32_t r[4], uint32_t saddr) {
    asm volatile("ldmatrix.sync.aligned.m8n8.x4.shared.b16 {%0,%1,%2,%3}, [%4];"
                 : "=r"(r[0]), "=r"(r[1]), "=r"(r[2]), "=r"(r[3]) : "r"(saddr));
}

__device__ __forceinline__ uint32_t pack_bf2(float x, float y) {
    __nv_bfloat162 b2 = __float22bfloat162_rn(make_float2(x, y));
    return *(uint32_t*)&b2;
}

// ---------------- fused prep: pad h, edge MLP, cast Ew, zero msg ----------------
#define PREP_PAD_BLKS 5000                  // N_NODES*H/256
#define PREP_MLP_BLKS (E_PAD / 4)           // 10016
#define PREP_B_BLKS 1024                    // H*HH/256
#define PREP_ZERO_BLKS 5000                 // N_NODES*H/256
#define PREP_GRID (PREP_PAD_BLKS + PREP_MLP_BLKS + PREP_B_BLKS + PREP_ZERO_BLKS)

__global__ void k_prep(const float* __restrict__ nf, const float* __restrict__ ef,
                       const float* __restrict__ Wm, const float* __restrict__ bm,
                       const float* __restrict__ Ew) {
    int b = blockIdx.x;
    int tid = threadIdx.x;
    if (b < PREP_PAD_BLKS) {
        int idx = b * 256 + tid;
        int n = idx >> 6, c = idx & 63;
        g_h[idx] = (c < F_ATOM) ? nf[n * F_ATOM + c] : 0.f;
    } else if (b < PREP_PAD_BLKS + PREP_MLP_BLKS) {
        __shared__ float s_ef[4][F_BOND];
        int eb = b - PREP_PAD_BLKS;
        int sub = tid >> 6, i = tid & 63;
        int e = eb * 4 + sub;
        if (i < F_BOND) s_ef[sub][i] = (e < N_EDGES) ? ef[e * F_BOND + i] : 0.f;
        __syncthreads();
        float v = bm[i];
#pragma unroll
        for (int f = 0; f < F_BOND; f++) v += s_ef[sub][f] * Wm[f * H + i];
        v = fmaxf(v, 0.f);
        if (e >= N_EDGES) v = 0.f;
        g_mlpb[e * H + i] = __float2bfloat16_rn(v);
    } else if (b < PREP_PAD_BLKS + PREP_MLP_BLKS + PREP_B_BLKS) {
        int o = (b - PREP_PAD_BLKS - PREP_MLP_BLKS) * 256 + tid;
        g_Ewb[o] = __float2bfloat16_rn(Ew[o]);
    } else {
        int idx = (b - PREP_PAD_BLKS - PREP_MLP_BLKS - PREP_B_BLKS) * 256 + tid;
        g_msg[idx] = 0.f;
    }
}

// ============================================================================
// Fused message step v3: A-fragment formed in REGISTERS (no o smem staging).
//   msg[e,i] += sum_{m in seg, j} (mlp[e,m]*h[rng[e],j]) * Ew[m, i*64+j]
// Grid (E_PAD/128, KSEG). 8 warps; warp = 16 edge-rows x 64 cols.
// Per lane: h fp32 for rows {g, g+8}, j in kk*16+{2tg,2tg+1,2tg+8,2tg+9}.
// Per chunk: 2 broadcast mlp LDS, 8 FMUL + 4 packs per kk for A; B chunk
// double-buffered in smem (one sync/chunk), 16 B-ldsm + 32 MMA per warp.
// ============================================================================
__global__ void __launch_bounds__(256, 2) k_medge(const int* __restrict__ dom,
                                                  const int* __restrict__ rng) {
    __shared__ __align__(16) __nv_bfloat16 s_mlpT[64 * 128];  // [m][e], 16 KB
    __shared__ __align__(16) uint32_t s_ew[2][64 * 36];       // Ew chunk, double buffer, 18 KB
    __shared__ int s_dom[128];
    int tid = threadIdx.x;
    int e0 = blockIdx.x * 128;
    int m0 = blockIdx.y * MCH;

    // mlp tile transposed into smem ([m][e])
    {
        int e = tid >> 1, half = tid & 1;
        const uint4* src = (const uint4*)(g_mlpb + (size_t)(e0 + e) * H + half * 32);
        uint4 v[4];
        v[0] = src[0]; v[1] = src[1]; v[2] = src[2]; v[3] = src[3];
        const __nv_bfloat16* bv = (const __nv_bfloat16*)v;
#pragma unroll
        for (int k = 0; k < 32; k++)
            s_mlpT[(half * 32 + k) * 128 + e] = bv[k];
    }
    if (tid < 128) {
        int ge = e0 + tid;
        s_dom[tid] = (ge < N_EDGES) ? dom[ge] : 0;
    }

    int lane = tid & 31, wid = tid >> 5;
    int g_ = lane >> 2, tg = lane & 3;
    int wm = wid * 16;

    // gather h into registers: rows {wm+g, wm+g+8}, 16 j-values each
    float h[2][16];
#pragma unroll
    for (int rs = 0; rs < 2; rs++) {
        int r = wm + g_ + rs * 8;
        int ge = e0 + r;
        int rr = (ge < N_EDGES) ? __ldg(&rng[ge]) : 0;
        const float* hrow = g_h + rr * H;
#pragma unroll
        for (int kk = 0; kk < 4; kk++) {
            float2 lo = *(const float2*)(hrow + kk * 16 + 2 * tg);
            float2 hi = *(const float2*)(hrow + kk * 16 + 8 + 2 * tg);
            h[rs][kk * 4 + 0] = lo.x;
            h[rs][kk * 4 + 1] = lo.y;
            h[rs][kk * 4 + 2] = hi.x;
            h[rs][kk * 4 + 3] = hi.y;
        }
    }

    // prefetch first Ew chunk (512 uint4 per chunk; 2 per thread)
    uint4 pf0, pf1;
    {
        const uint4* src = (const uint4*)(g_Ewb + (size_t)m0 * HH);
        pf0 = src[2 * tid];
        pf1 = src[2 * tid + 1];
    }
    __syncthreads();   // s_mlpT, s_dom ready

    int lrow = (lane & 7) + ((lane >> 3) & 1) * 8;
    int lcol = (lane >> 4) * 4;
    int i0 = 2 * tid, i1 = 2 * tid + 1;
    uint32_t so0 = (uint32_t)__cvta_generic_to_shared(&s_ew[0][0]);
    uint32_t so1 = (uint32_t)__cvta_generic_to_shared(&s_ew[1][0]);

    float c[8][4] = {};
    int p = 0;

    for (int mc = 0; mc < MCH; mc++) {
        int m = m0 + mc;
        // store prefetched Ew chunk into buffer p
        *(uint4*)&s_ew[p][(i0 >> 3) * 36 + (i0 & 7) * 4] = pf0;
        *(uint4*)&s_ew[p][(i1 >> 3) * 36 + (i1 & 7) * 4] = pf1;
        __syncthreads();
        // prefetch next chunk during compute
        if (mc < MCH - 1) {
            const uint4* src = (const uint4*)(g_Ewb + (size_t)(m + 1) * HH);
            pf0 = src[2 * tid];
            pf1 = src[2 * tid + 1];
        }
        // broadcast mlp scalars for this chunk
        float am0 = __bfloat162float(s_mlpT[m * 128 + wm + g_]);
        float am8 = __bfloat162float(s_mlpT[m * 128 + wm + g_ + 8]);
        uint32_t sew_u32 = p ? so1 : so0;

#pragma unroll
        for (int kk = 0; kk < 4; kk++) {
            // A-fragment in registers: a0/a2 row g, a1/a3 row g+8
            uint32_t a[4];
            a[0] = pack_bf2(am0 * h[0][kk * 4 + 0], am0 * h[0][kk * 4 + 1]);
            a[1] = pack_bf2(am8 * h[1][kk * 4 + 0], am8 * h[1][kk * 4 + 1]);
            a[2] = pack_bf2(am0 * h[0][kk * 4 + 2], am0 * h[0][kk * 4 + 3]);
            a[3] = pack_bf2(am8 * h[1][kk * 4 + 2], am8 * h[1][kk * 4 + 3]);
#pragma unroll
            for (int nt = 0; nt < 4; nt++) {
                uint32_t bq[4];
                uint32_t addr = sew_u32 + ((nt * 16 + lrow) * 36 + kk * 8 + lcol) * 4;
                ldsm_x4(bq, addr);
                mma_bf16_16816(c[nt * 2 + 0], a, bq[0], bq[2]);
                mma_bf16_16816(c[nt * 2 + 1], a, bq[1], bq[3]);
            }
        }
        p ^= 1;
    }

    // flush (padded edges: mlp=0 -> c=0, dom=0 safe)
    int d0 = s_dom[wm + g_];
    int d1 = s_dom[wm + g_ + 8];
#pragma unroll
    for (int ni = 0; ni < 8; ni++) {
        int col = ni * 8 + tg * 2;
        atomicAdd(&g_msg[d0 * H + col + 0], c[ni][0]);
        atomicAdd(&g_msg[d0 * H + col + 1], c[ni][1]);
        atomicAdd(&g_msg[d1 * H + col + 0], c[ni][2]);
        atomicAdd(&g_msg[d1 * H + col + 1], c[ni][3]);
    }
}

// h = selu(msg @ Wu + bu + h); resets msg. 32 nodes/block, 8 nodes/thread. (R13-proven.)
__global__ void __launch_bounds__(256) k_update(const float* __restrict__ Wu,
                                                const float* __restrict__ bu) {
    __shared__ __align__(16) float s_m[32][64];
    int tid = threadIdx.x;
    int i = tid & 63, sub = tid >> 6;
    int n0 = blockIdx.x * 32;
    float4* gm = (float4*)(g_msg + n0 * H);
    float4* sm4 = (float4*)s_m;
    const float4 z4 = make_float4(0.f, 0.f, 0.f, 0.f);
#pragma unroll
    for (int it = 0; it < 2; it++) {
        int idx = it * 256 + tid;
        sm4[idx] = gm[idx];
        gm[idx] = z4;
    }
    __syncthreads();
    float b = bu[i];
    float acc[8] = {b, b, b, b, b, b, b, b};
#pragma unroll 4
    for (int kc = 0; kc < 16; kc++) {
        int k = kc * 4;
        float w0 = Wu[(k + 0) * H + i];
        float w1 = Wu[(k + 1) * H + i];
        float w2 = Wu[(k + 2) * H + i];
        float w3 = Wu[(k + 3) * H + i];
#pragma unroll
        for (int u = 0; u < 8; u++) {
            float4 m4 = *(const float4*)&s_m[sub * 8 + u][k];
            acc[u] = fmaf(m4.x, w0, acc[u]);
            acc[u] = fmaf(m4.y, w1, acc[u]);
            acc[u] = fmaf(m4.z, w2, acc[u]);
            acc[u] = fmaf(m4.w, w3, acc[u]);
        }
    }
#pragma unroll
    for (int u = 0; u < 8; u++) {
        int idx = (n0 + sub * 8 + u) * H + i;
        g_h[idx] = selu_f(acc[u] + g_h[idx]);
    }
}

// act = selu((h @ Wae + bae) @ WR + bR); 32 nodes/block, 8/thread; zeroes gsum. (R13-proven.)
__global__ void __launch_bounds__(256) k_embed(const float* __restrict__ Wae,
                                               const float* __restrict__ bae,
                                               const float* __restrict__ WR,
                                               const float* __restrict__ bR) {
    __shared__ __align__(16) float s_h[32][64];
    __shared__ __align__(16) float s_ae[32][64];
    int tid = threadIdx.x;
    if (blockIdx.x < 128) g_gsum[blockIdx.x * 256 + tid] = 0.f;
    int i = tid & 63, sub = tid >> 6;
    int n0 = blockIdx.x * 32;
    const float4* gh = (const float4*)(g_h + n0 * H);
    float4* sh4 = (float4*)s_h;
#pragma unroll
    for (int it = 0; it < 2; it++) {
        int idx = it * 256 + tid;
        sh4[idx] = gh[idx];
    }
    __syncthreads();
    float b1 = bae[i];
    float ae[8] = {b1, b1, b1, b1, b1, b1, b1, b1};
#pragma unroll 4
    for (int kc = 0; kc < 16; kc++) {
        int k = kc * 4;
        float w0 = Wae[(k + 0) * H + i];
        float w1 = Wae[(k + 1) * H + i];
        float w2 = Wae[(k + 2) * H + i];
        float w3 = Wae[(k + 3) * H + i];
#pragma unroll
        for (int u = 0; u < 8; u++) {
            float4 m4 = *(const float4*)&s_h[sub * 8 + u][k];
            ae[u] = fmaf(m4.x, w0, ae[u]);
            ae[u] = fmaf(m4.y, w1, ae[u]);
            ae[u] = fmaf(m4.z, w2, ae[u]);
            ae[u] = fmaf(m4.w, w3, ae[u]);
        }
    }
#pragma unroll
    for (int u = 0; u < 8; u++) s_ae[sub * 8 + u][i] = ae[u];
    __syncthreads();
    float b2 = bR[i];
    float acc[8] = {b2, b2, b2, b2, b2, b2, b2, b2};
#pragma unroll 4
    for (int kc = 0; kc < 16; kc++) {
        int k = kc * 4;
        float w0 = WR[(k + 0) * H + i];
        float w1 = WR[(k + 1) * H + i];
        float w2 = WR[(k + 2) * H + i];
        float w3 = WR[(k + 3) * H + i];
#pragma unroll
        for (int u = 0; u < 8; u++) {
            float4 m4 = *(const float4*)&s_ae[sub * 8 + u][k];
            acc[u] = fmaf(m4.x, w0, acc[u]);
            acc[u] = fmaf(m4.y, w1, acc[u]);
            acc[u] = fmaf(m4.z, w2, acc[u]);
            acc[u] = fmaf(m4.w, w3, acc[u]);
        }
    }
#pragma unroll
    for (int u = 0; u < 8; u++)
        g_act[(n0 + sub * 8 + u) * H + i] = selu_f(acc[u]);
}

// segment-sum act over graph_id
__global__ void k_graphsum(const int* __restrict__ gid) {
    int idx = blockIdx.x * blockDim.x + threadIdx.x;
    if (idx >= N_NODES * H) return;
    int n = idx >> 6, i = idx & 63;
    atomicAdd(&g_gsum[gid[n] * H + i], g_act[idx]);
}

// out[b] = relu(tanh(gsum[b]) @ Wmlp + bmlp) @ Wout + bout
__global__ void k_readout(const float* __restrict__ Wmlp, const float* __restrict__ bmlp,
                          const float* __restrict__ Wout, const float* __restrict__ bout,
                          float* __restrict__ out) {
    __shared__ float s_ge[64];
    __shared__ float s_red[64];
    int b = blockIdx.x, i = threadIdx.x;
    s_ge[i] = tanhf(g_gsum[b * H + i]);
    __syncthreads();
    float acc = bmlp[i];
#pragma unroll 8
    for (int k = 0; k < 64; k++) acc = fmaf(s_ge[k], Wmlp[k * H + i], acc);
    float p = fmaxf(acc, 0.f) * Wout[i];
    s_red[i] = p;
    __syncthreads();
#pragma unroll
    for (int s = 32; s > 0; s >>= 1) {
        if (i < s) s_red[i] += s_red[i + s];
        __syncthreads();
    }
    if (i == 0) out[b] = s_red[0] + bout[0];
}

extern "C" void kernel_launch(void* const* d_in, const int* in_sizes, int n_in,
                              void* d_out, int out_size) {
    const float* node_features = (const float*)d_in[0];
    const float* edge_features = (const float*)d_in[1];
    const int*   edge_domain   = (const int*)d_in[2];
    const int*   edge_range    = (const int*)d_in[3];
    const int*   graph_id      = (const int*)d_in[4];
    const float* Wm   = (const float*)d_in[5];
    const float* bm   = (const float*)d_in[6];
    const float* Ew   = (const float*)d_in[7];
    const float* Wu0  = (const float*)d_in[8];
    const float* bu0  = (const float*)d_in[9];
    const float* Wu1  = (const float*)d_in[10];
    const float* bu1  = (const float*)d_in[11];
    const float* Wae  = (const float*)d_in[12];
    const float* bae  = (const float*)d_in[13];
    const float* WR   = (const float*)d_in[14];
    const float* bR   = (const float*)d_in[15];
    const float* Wmlp = (const float*)d_in[16];
    const float* bmlp = (const float*)d_in[17];
    const float* Wout = (const float*)d_in[18];
    const float* bout = (const float*)d_in[19];
    float* out = (float*)d_out;

    // fused prep: pad h, edge MLP, cast Ew to bf16, zero g_msg
    k_prep<<<PREP_GRID, 256>>>(node_features, edge_features, Wm, bm, Ew);

    // message passing steps: fused on-the-fly GEMM, register A-fragments
    const float* Wus[2] = {Wu0, Wu1};
    const float* bus[2] = {bu0, bu1};
    dim3 gM(E_PAD / 128, KSEG);
    for (int t = 0; t < 2; t++) {
        k_medge<<<gM, 256>>>(edge_domain, edge_range);
        k_update<<<N_NODES / 32, 256>>>(Wus[t], bus[t]);  // also re-zeroes g_msg
    }

    // readout
    k_embed<<<N_NODES / 32, 256>>>(Wae, bae, WR, bR);     // also zeroes g_gsum
    k_graphsum<<<(N_NODES * H + 255) / 256, 256>>>(graph_id);
    k_readout<<<BGRAPH, 64>>>(Wmlp, bmlp, Wout, bout, out);
}